// round 1
// baseline (speedup 1.0000x reference)
#include <cuda_runtime.h>
#include <math.h>

#define BATCH 4
#define CHAN  256
#define DIM   128
#define NTOK  4096   // 64*64

// ---------------- scratch (device globals; no allocation allowed) ----------------
__device__ float g_theta[BATCH * DIM * NTOK];
__device__ float g_phi  [BATCH * DIM * NTOK];
__device__ float g_gx   [BATCH * DIM * NTOK];
__device__ float g_f    [(size_t)BATCH * NTOK * NTOK];   // 268 MB attention matrix
__device__ float g_y    [BATCH * DIM * NTOK];
__device__ float g_wy   [BATCH * CHAN * NTOK];
__device__ float g_mean [CHAN];
__device__ float g_istd [CHAN];

// ---------------- generic tiled fp32 GEMM ----------------
// C[m,n] = sum_k A[m,k] * B[k,n] (+ bias[m])
// TA=false: A stored [M,K] row-major.  TA=true: A stored [K,M] row-major (A^T access).
// TB=false: B stored [K,N] row-major.  TB=true: B stored [N,K] row-major (B^T access).
// Tiles: 128x128 output per block, BK=8, 256 threads, 8x8 micro-tile split as 2x2 groups of 4x4.
template<bool TA, bool TB>
__global__ __launch_bounds__(256, 2)
void sgemm(const float* __restrict__ A, const float* __restrict__ B,
           const float* __restrict__ bias, float* __restrict__ C,
           int M, int N, int K, size_t sA, size_t sB, size_t sC)
{
    __shared__ float As[8][132];
    __shared__ float Bs[8][132];

    A += (size_t)blockIdx.z * sA;
    B += (size_t)blockIdx.z * sB;
    C += (size_t)blockIdx.z * sC;

    const int m0 = blockIdx.y * 128;
    const int n0 = blockIdx.x * 128;
    const int tid = threadIdx.x;
    const int tx = tid & 15;     // 0..15 -> column groups
    const int ty = tid >> 4;     // 0..15 -> row groups

    float acc[8][8] = {};

    for (int k0 = 0; k0 < K; k0 += 8) {
        // ---- load A tile into As[k][m] ----
        if (TA) {
            int r = tid >> 5;              // 0..7  (k)
            int c = (tid & 31) << 2;       // 0..124 (m)
            float4 v = *(const float4*)(A + (size_t)(k0 + r) * M + (m0 + c));
            *(float4*)&As[r][c] = v;
        } else {
            int r = tid >> 1;              // 0..127 (m)
            int q = (tid & 1) << 2;        // 0 or 4 (k)
            float4 v = *(const float4*)(A + (size_t)(m0 + r) * K + (k0 + q));
            As[q + 0][r] = v.x; As[q + 1][r] = v.y;
            As[q + 2][r] = v.z; As[q + 3][r] = v.w;
        }
        // ---- load B tile into Bs[k][n] ----
        if (TB) {
            int r = tid >> 1;              // 0..127 (n)
            int q = (tid & 1) << 2;        // 0 or 4 (k)
            float4 v = *(const float4*)(B + (size_t)(n0 + r) * K + (k0 + q));
            Bs[q + 0][r] = v.x; Bs[q + 1][r] = v.y;
            Bs[q + 2][r] = v.z; Bs[q + 3][r] = v.w;
        } else {
            int r = tid >> 5;              // 0..7  (k)
            int c = (tid & 31) << 2;       // 0..124 (n)
            float4 v = *(const float4*)(B + (size_t)(k0 + r) * N + (n0 + c));
            *(float4*)&Bs[r][c] = v;
        }
        __syncthreads();

        #pragma unroll
        for (int k = 0; k < 8; k++) {
            float a[8], b[8];
            *(float4*)&a[0] = *(float4*)&As[k][ty * 4];
            *(float4*)&a[4] = *(float4*)&As[k][ty * 4 + 64];
            *(float4*)&b[0] = *(float4*)&Bs[k][tx * 4];
            *(float4*)&b[4] = *(float4*)&Bs[k][tx * 4 + 64];
            #pragma unroll
            for (int i = 0; i < 8; i++)
                #pragma unroll
                for (int j = 0; j < 8; j++)
                    acc[i][j] = fmaf(a[i], b[j], acc[i][j]);
        }
        __syncthreads();
    }

    // ---- epilogue ----
    #pragma unroll
    for (int i = 0; i < 8; i++) {
        int m = m0 + ((i < 4) ? (ty * 4 + i) : (64 + ty * 4 + i - 4));
        float bv = bias ? bias[m] : 0.0f;
        #pragma unroll
        for (int jg = 0; jg < 2; jg++) {
            int n = n0 + tx * 4 + jg * 64;
            float4 o;
            o.x = acc[i][jg * 4 + 0] + bv;
            o.y = acc[i][jg * 4 + 1] + bv;
            o.z = acc[i][jg * 4 + 2] + bv;
            o.w = acc[i][jg * 4 + 3] + bv;
            *(float4*)(C + (size_t)m * N + n) = o;
        }
    }
}

// ---------------- row softmax over 4096-wide rows ----------------
__global__ __launch_bounds__(256)
void softmax_rows(float* __restrict__ f)
{
    float4* row = (float4*)(f + (size_t)blockIdx.x * NTOK);
    const int t = threadIdx.x;
    __shared__ float red[8];

    float4 v[4];
    float mx = -3.4e38f;
    #pragma unroll
    for (int i = 0; i < 4; i++) {
        v[i] = row[t + i * 256];
        mx = fmaxf(mx, fmaxf(fmaxf(v[i].x, v[i].y), fmaxf(v[i].z, v[i].w)));
    }
    #pragma unroll
    for (int o = 16; o; o >>= 1) mx = fmaxf(mx, __shfl_xor_sync(0xffffffffu, mx, o));
    if ((t & 31) == 0) red[t >> 5] = mx;
    __syncthreads();
    mx = red[0];
    #pragma unroll
    for (int i = 1; i < 8; i++) mx = fmaxf(mx, red[i]);

    float s = 0.0f;
    #pragma unroll
    for (int i = 0; i < 4; i++) {
        v[i].x = __expf(v[i].x - mx); v[i].y = __expf(v[i].y - mx);
        v[i].z = __expf(v[i].z - mx); v[i].w = __expf(v[i].w - mx);
        s += (v[i].x + v[i].y) + (v[i].z + v[i].w);
    }
    #pragma unroll
    for (int o = 16; o; o >>= 1) s += __shfl_xor_sync(0xffffffffu, s, o);
    __syncthreads();                 // red reuse
    if ((t & 31) == 0) red[t >> 5] = s;
    __syncthreads();
    s = ((red[0] + red[1]) + (red[2] + red[3])) + ((red[4] + red[5]) + (red[6] + red[7]));
    float inv = 1.0f / s;

    #pragma unroll
    for (int i = 0; i < 4; i++) {
        v[i].x *= inv; v[i].y *= inv; v[i].z *= inv; v[i].w *= inv;
        row[t + i * 256] = v[i];
    }
}

// ---------------- BatchNorm statistics (per channel over B*H*W = 16384) ----------------
__global__ __launch_bounds__(256)
void bn_stats(const float* __restrict__ wy)
{
    const int c = blockIdx.x;
    const int t = threadIdx.x;
    float s1 = 0.0f, s2 = 0.0f;
    #pragma unroll
    for (int b = 0; b < BATCH; b++) {
        const float* p = wy + ((size_t)(b * CHAN + c) << 12);
        for (int i = t; i < NTOK; i += 256) {
            float x = p[i];
            s1 += x;
            s2 += x * x;
        }
    }
    #pragma unroll
    for (int o = 16; o; o >>= 1) {
        s1 += __shfl_xor_sync(0xffffffffu, s1, o);
        s2 += __shfl_xor_sync(0xffffffffu, s2, o);
    }
    __shared__ float r1[8], r2[8];
    if ((t & 31) == 0) { r1[t >> 5] = s1; r2[t >> 5] = s2; }
    __syncthreads();
    if (t == 0) {
        s1 = 0.0f; s2 = 0.0f;
        #pragma unroll
        for (int i = 0; i < 8; i++) { s1 += r1[i]; s2 += r2[i]; }
        float mean = s1 * (1.0f / 16384.0f);
        float var  = s2 * (1.0f / 16384.0f) - mean * mean;
        g_mean[c] = mean;
        g_istd[c] = rsqrtf(var + 1e-5f);
    }
}

// ---------------- BN apply + residual ----------------
__global__ __launch_bounds__(256)
void bn_apply(const float* __restrict__ wy, const float* __restrict__ x,
              const float* __restrict__ gamma, const float* __restrict__ beta,
              float* __restrict__ out)
{
    int i4 = blockIdx.x * 256 + threadIdx.x;       // index over float4 (4096/4=1024 per channel row)
    int c = (i4 >> 10) & (CHAN - 1);
    float is = g_istd[c];
    float ga = gamma[c] * is;
    float be = beta[c] - g_mean[c] * ga;
    float4 w = ((const float4*)wy)[i4];
    float4 xx = ((const float4*)x)[i4];
    float4 o;
    o.x = w.x * ga + be + xx.x;
    o.y = w.y * ga + be + xx.y;
    o.z = w.z * ga + be + xx.z;
    o.w = w.w * ga + be + xx.w;
    ((float4*)out)[i4] = o;
}

// ---------------- launch ----------------
extern "C" void kernel_launch(void* const* d_in, const int* in_sizes, int n_in,
                              void* d_out, int out_size)
{
    const float* x       = (const float*)d_in[0];
    const float* g_w     = (const float*)d_in[1];
    const float* g_b     = (const float*)d_in[2];
    const float* theta_w = (const float*)d_in[3];
    const float* theta_b = (const float*)d_in[4];
    const float* phi_w   = (const float*)d_in[5];
    const float* phi_b   = (const float*)d_in[6];
    const float* w_w     = (const float*)d_in[7];
    const float* w_b     = (const float*)d_in[8];
    const float* gamma   = (const float*)d_in[9];
    const float* beta    = (const float*)d_in[10];
    float* out = (float*)d_out;

    float *theta, *phi, *gx, *f, *y, *wy;
    cudaGetSymbolAddress((void**)&theta, g_theta);
    cudaGetSymbolAddress((void**)&phi,   g_phi);
    cudaGetSymbolAddress((void**)&gx,    g_gx);
    cudaGetSymbolAddress((void**)&f,     g_f);
    cudaGetSymbolAddress((void**)&y,     g_y);
    cudaGetSymbolAddress((void**)&wy,    g_wy);

    const size_t sX  = (size_t)CHAN * NTOK;   // x batch stride
    const size_t sD  = (size_t)DIM * NTOK;    // [D,N] batch stride
    const size_t sF  = (size_t)NTOK * NTOK;   // f batch stride

    // projections: [D,C] x [C,N] -> [D,N]
    sgemm<false, false><<<dim3(32, 1, BATCH), 256>>>(theta_w, x, theta_b, theta,
                                                     DIM, NTOK, CHAN, 0, sX, sD);
    sgemm<false, false><<<dim3(32, 1, BATCH), 256>>>(phi_w,   x, phi_b,   phi,
                                                     DIM, NTOK, CHAN, 0, sX, sD);
    sgemm<false, false><<<dim3(32, 1, BATCH), 256>>>(g_w,     x, g_b,     gx,
                                                     DIM, NTOK, CHAN, 0, sX, sD);

    // f[n,m] = sum_d theta[d,n] * phi[d,m]   (A^T B, K=128)
    sgemm<true, false><<<dim3(32, 32, BATCH), 256>>>(theta, phi, nullptr, f,
                                                     NTOK, NTOK, DIM, sD, sD, sF);

    // row softmax
    softmax_rows<<<BATCH * NTOK, 256>>>(f);

    // y[d,n] = sum_m gx[d,m] * P[n,m]   (A B^T, K=4096)
    sgemm<false, true><<<dim3(32, 1, BATCH), 256>>>(gx, f, nullptr, y,
                                                    DIM, NTOK, NTOK, sD, sF, sD);

    // wy[c,n] = sum_d w_w[c,d] * y[d,n] + w_b[c]
    sgemm<false, false><<<dim3(32, 2, BATCH), 256>>>(w_w, y, w_b, wy,
                                                     CHAN, NTOK, DIM, 0, sD, sX);

    // batchnorm + residual
    bn_stats<<<CHAN, 256>>>(wy);
    bn_apply<<<(BATCH * CHAN * NTOK / 4) / 256, 256>>>(wy, x, gamma, beta, out);
}

// round 3
// speedup vs baseline: 1.8228x; 1.8228x over previous
#include <cuda_runtime.h>
#include <cuda_bf16.h>
#include <cstdint>
#include <math.h>

#define BATCH 4
#define CHAN  256
#define DIM   128
#define NTOK  4096

// ============================ scratch ============================
__device__ float g_f[(size_t)BATCH * NTOK * NTOK];     // logits (fp32)
__device__ __nv_bfloat16 g_p_hi[(size_t)BATCH * NTOK * NTOK];
__device__ __nv_bfloat16 g_p_lo[(size_t)BATCH * NTOK * NTOK];
__device__ __nv_bfloat16 g_th_hi[BATCH * NTOK * DIM];  // theta token-major [n,d]
__device__ __nv_bfloat16 g_th_lo[BATCH * NTOK * DIM];
__device__ __nv_bfloat16 g_ph_hi[BATCH * NTOK * DIM];  // phi token-major [m,d]
__device__ __nv_bfloat16 g_ph_lo[BATCH * NTOK * DIM];
__device__ __nv_bfloat16 g_g_hi[BATCH * DIM * NTOK];   // g d-major [d,m]
__device__ __nv_bfloat16 g_g_lo[BATCH * DIM * NTOK];
__device__ float g_y [BATCH * NTOK * DIM];             // y token-major [n,d]
__device__ float g_wy[BATCH * CHAN * NTOK];
__device__ float g_mean[CHAN];
__device__ float g_istd[CHAN];

// ============================ helpers ============================
__device__ __forceinline__ uint32_t smem_to_u32(const void* p) {
    uint32_t a;
    asm("{ .reg .u64 t; cvta.to.shared.u64 t, %1; cvt.u32.u64 %0, t; }" : "=r"(a) : "l"(p));
    return a;
}

__device__ __forceinline__ void ldsm_x4(uint32_t* r, uint32_t addr) {
    asm volatile("ldmatrix.sync.aligned.m8n8.x4.shared.b16 {%0,%1,%2,%3}, [%4];"
                 : "=r"(r[0]), "=r"(r[1]), "=r"(r[2]), "=r"(r[3]) : "r"(addr));
}

__device__ __forceinline__ void mma_bf16(float* c, const uint32_t* a, const uint32_t* b) {
    asm volatile("mma.sync.aligned.m16n8k16.row.col.f32.bf16.bf16.f32 "
                 "{%0,%1,%2,%3}, {%4,%5,%6,%7}, {%8,%9}, {%0,%1,%2,%3};"
                 : "+f"(c[0]), "+f"(c[1]), "+f"(c[2]), "+f"(c[3])
                 : "r"(a[0]), "r"(a[1]), "r"(a[2]), "r"(a[3]), "r"(b[0]), "r"(b[1]));
}

__device__ __forceinline__ void split_write4(__nv_bfloat16* hi, __nv_bfloat16* lo,
                                             float a, float b, float c, float d) {
    __nv_bfloat16 h0 = __float2bfloat16_rn(a), h1 = __float2bfloat16_rn(b);
    __nv_bfloat16 h2 = __float2bfloat16_rn(c), h3 = __float2bfloat16_rn(d);
    __nv_bfloat16 l0 = __float2bfloat16_rn(a - __bfloat162float(h0));
    __nv_bfloat16 l1 = __float2bfloat16_rn(b - __bfloat162float(h1));
    __nv_bfloat16 l2 = __float2bfloat16_rn(c - __bfloat162float(h2));
    __nv_bfloat16 l3 = __float2bfloat16_rn(d - __bfloat162float(h3));
    *(__nv_bfloat162*)(hi + 0) = __nv_bfloat162(h0, h1);
    *(__nv_bfloat162*)(hi + 2) = __nv_bfloat162(h2, h3);
    *(__nv_bfloat162*)(lo + 0) = __nv_bfloat162(l0, l1);
    *(__nv_bfloat162*)(lo + 2) = __nv_bfloat162(l2, l3);
}

// ============================ projections (fp32 SIMT) ============================
// token-major output: C[m=token][n=dim] = sum_c x[c,token] * W[dim,c] + bias[dim]
__global__ __launch_bounds__(256, 2)
void proj_nd(const float* __restrict__ x, const float* __restrict__ W,
             const float* __restrict__ bias,
             __nv_bfloat16* __restrict__ out_hi, __nv_bfloat16* __restrict__ out_lo)
{
    __shared__ float As[8][132];
    __shared__ float Bs[8][132];
    const int b = blockIdx.z;
    const int m0 = blockIdx.x * 128;
    const float* A = x + (size_t)b * CHAN * NTOK;   // [C, NTOK]
    const int tid = threadIdx.x;
    const int tx = tid & 15, ty = tid >> 4;

    float acc[8][8] = {};
    for (int k0 = 0; k0 < CHAN; k0 += 8) {
        { int r = tid >> 5; int c = (tid & 31) << 2;
          float4 v = *(const float4*)(A + (size_t)(k0 + r) * NTOK + m0 + c);
          *(float4*)&As[r][c] = v; }
        { int r = tid >> 1; int q = (tid & 1) << 2;
          float4 v = *(const float4*)(W + (size_t)r * CHAN + k0 + q);
          Bs[q + 0][r] = v.x; Bs[q + 1][r] = v.y; Bs[q + 2][r] = v.z; Bs[q + 3][r] = v.w; }
        __syncthreads();
        #pragma unroll
        for (int k = 0; k < 8; k++) {
            float a[8], bb[8];
            *(float4*)&a[0] = *(float4*)&As[k][ty * 4];
            *(float4*)&a[4] = *(float4*)&As[k][ty * 4 + 64];
            *(float4*)&bb[0] = *(float4*)&Bs[k][tx * 4];
            *(float4*)&bb[4] = *(float4*)&Bs[k][tx * 4 + 64];
            #pragma unroll
            for (int i = 0; i < 8; i++)
                #pragma unroll
                for (int j = 0; j < 8; j++)
                    acc[i][j] = fmaf(a[i], bb[j], acc[i][j]);
        }
        __syncthreads();
    }
    float bv[8];
    #pragma unroll
    for (int jg = 0; jg < 2; jg++)
        #pragma unroll
        for (int j = 0; j < 4; j++) bv[jg * 4 + j] = bias[tx * 4 + jg * 64 + j];
    #pragma unroll
    for (int i = 0; i < 8; i++) {
        int m = m0 + ((i < 4) ? (ty * 4 + i) : (64 + ty * 4 + i - 4));
        __nv_bfloat16* oh = out_hi + ((size_t)b * NTOK + m) * DIM;
        __nv_bfloat16* ol = out_lo + ((size_t)b * NTOK + m) * DIM;
        #pragma unroll
        for (int jg = 0; jg < 2; jg++) {
            int n = tx * 4 + jg * 64;
            split_write4(oh + n, ol + n,
                         acc[i][jg * 4 + 0] + bv[jg * 4 + 0],
                         acc[i][jg * 4 + 1] + bv[jg * 4 + 1],
                         acc[i][jg * 4 + 2] + bv[jg * 4 + 2],
                         acc[i][jg * 4 + 3] + bv[jg * 4 + 3]);
        }
    }
}

// d-major output: C[m=dim][n=token] = sum_c W[dim,c] * x[c,token] + bias[dim]
__global__ __launch_bounds__(256, 2)
void proj_dn(const float* __restrict__ x, const float* __restrict__ W,
             const float* __restrict__ bias,
             __nv_bfloat16* __restrict__ out_hi, __nv_bfloat16* __restrict__ out_lo)
{
    __shared__ float As[8][132];
    __shared__ float Bs[8][132];
    const int b = blockIdx.z;
    const int n0 = blockIdx.x * 128;
    const float* B = x + (size_t)b * CHAN * NTOK;
    const int tid = threadIdx.x;
    const int tx = tid & 15, ty = tid >> 4;

    float acc[8][8] = {};
    for (int k0 = 0; k0 < CHAN; k0 += 8) {
        { int r = tid >> 1; int q = (tid & 1) << 2;
          float4 v = *(const float4*)(W + (size_t)r * CHAN + k0 + q);
          As[q + 0][r] = v.x; As[q + 1][r] = v.y; As[q + 2][r] = v.z; As[q + 3][r] = v.w; }
        { int r = tid >> 5; int c = (tid & 31) << 2;
          float4 v = *(const float4*)(B + (size_t)(k0 + r) * NTOK + n0 + c);
          *(float4*)&Bs[r][c] = v; }
        __syncthreads();
        #pragma unroll
        for (int k = 0; k < 8; k++) {
            float a[8], bb[8];
            *(float4*)&a[0] = *(float4*)&As[k][ty * 4];
            *(float4*)&a[4] = *(float4*)&As[k][ty * 4 + 64];
            *(float4*)&bb[0] = *(float4*)&Bs[k][tx * 4];
            *(float4*)&bb[4] = *(float4*)&Bs[k][tx * 4 + 64];
            #pragma unroll
            for (int i = 0; i < 8; i++)
                #pragma unroll
                for (int j = 0; j < 8; j++)
                    acc[i][j] = fmaf(a[i], bb[j], acc[i][j]);
        }
        __syncthreads();
    }
    #pragma unroll
    for (int i = 0; i < 8; i++) {
        int m = (i < 4) ? (ty * 4 + i) : (64 + ty * 4 + i - 4);
        float bvm = bias[m];
        __nv_bfloat16* oh = out_hi + ((size_t)b * DIM + m) * NTOK;
        __nv_bfloat16* ol = out_lo + ((size_t)b * DIM + m) * NTOK;
        #pragma unroll
        for (int jg = 0; jg < 2; jg++) {
            int n = n0 + tx * 4 + jg * 64;
            split_write4(oh + n, ol + n,
                         acc[i][jg * 4 + 0] + bvm, acc[i][jg * 4 + 1] + bvm,
                         acc[i][jg * 4 + 2] + bvm, acc[i][jg * 4 + 3] + bvm);
        }
    }
}

// ============================ unified mma.sync GEMM (C = A * B^T, split bf16) ============================
// A row-major [M, K] (hi/lo), B row-major [N, K] (hi/lo), C fp32 [M, N].
// CTA tile 128x128, K-chunk 64, 8 warps (2 rows x 4 cols), warp tile 64x32.
// Split product: C = Ah*Bh + Ah*Bl + Al*Bh  (lo*lo dropped, ~2^-16 rel).
#define GT_SMEM (4 * 128 * 64 * 2)   // 64 KB

__global__ __launch_bounds__(256, 2)
void mma_gemm_tt(const __nv_bfloat16* __restrict__ Ah, const __nv_bfloat16* __restrict__ Al,
                 const __nv_bfloat16* __restrict__ Bh, const __nv_bfloat16* __restrict__ Bl,
                 float* __restrict__ C,
                 int lda, int ldb, int ldc, int kchunks,
                 size_t strA, size_t strB, size_t strC)
{
    extern __shared__ __nv_bfloat16 smem[];
    __nv_bfloat16* sAh = smem;
    __nv_bfloat16* sAl = sAh + 128 * 64;
    __nv_bfloat16* sBh = sAl + 128 * 64;
    __nv_bfloat16* sBl = sBh + 128 * 64;
    const uint32_t uAh = smem_to_u32(sAh);
    const uint32_t uAl = smem_to_u32(sAl);
    const uint32_t uBh = smem_to_u32(sBh);
    const uint32_t uBl = smem_to_u32(sBl);

    const int tid = threadIdx.x;
    const int lane = tid & 31, wid = tid >> 5;
    const int wr = wid >> 2;          // 0..1 : 64-row slab
    const int wc = wid & 3;           // 0..3 : 32-col slab
    const int b  = blockIdx.z;
    const int m0 = blockIdx.y * 128;
    const int n0 = blockIdx.x * 128;

    const __nv_bfloat16* pAh = Ah + (size_t)b * strA;
    const __nv_bfloat16* pAl = Al + (size_t)b * strA;
    const __nv_bfloat16* pBh = Bh + (size_t)b * strB;
    const __nv_bfloat16* pBl = Bl + (size_t)b * strB;

    float acc[4][4][4] = {};

    // per-lane ldmatrix geometry (constant across chunk loop)
    const int a_rl = ((lane >> 3) & 1) * 8 + (lane & 7);  // row-in-16 for A
    const int a_cl = lane >> 4;                           // +chunk for A
    const int b_rl = (lane >> 4) * 8 + (lane & 7);        // row-in-16 for B
    const int b_cl = (lane >> 3) & 1;                     // +chunk for B

    for (int kc = 0; kc < kchunks; kc++) {
        const int k0 = kc * 64;
        // ---- load 4 tiles (128 rows x 64 bf16, swizzled chunks) ----
        #pragma unroll
        for (int i = tid; i < 1024; i += 256) {
            int r = i >> 3, c = i & 7;
            uint32_t so = (uint32_t)(r * 8 + (c ^ (r & 7))) * 8;   // offset in bf16 units
            size_t ga = (size_t)(m0 + r) * lda + k0 + c * 8;
            size_t gb = (size_t)(n0 + r) * ldb + k0 + c * 8;
            *(uint4*)(sAh + so) = *(const uint4*)(pAh + ga);
            *(uint4*)(sAl + so) = *(const uint4*)(pAl + ga);
            *(uint4*)(sBh + so) = *(const uint4*)(pBh + gb);
            *(uint4*)(sBl + so) = *(const uint4*)(pBl + gb);
        }
        __syncthreads();

        #pragma unroll
        for (int ks = 0; ks < 4; ks++) {
            const int kk8 = ks * 2;
            // ---- B fragments (4 n8 frags per half) ----
            uint32_t bh[4][2], bl[4][2];
            #pragma unroll
            for (int j2 = 0; j2 < 2; j2++) {
                int nrow = wc * 32 + j2 * 16 + b_rl;
                int c = kk8 + b_cl;
                uint32_t off = (uint32_t)(nrow * 8 + (c ^ (nrow & 7))) * 16;
                uint32_t r[4];
                ldsm_x4(r, uBh + off);
                bh[j2 * 2 + 0][0] = r[0]; bh[j2 * 2 + 0][1] = r[1];
                bh[j2 * 2 + 1][0] = r[2]; bh[j2 * 2 + 1][1] = r[3];
                ldsm_x4(r, uBl + off);
                bl[j2 * 2 + 0][0] = r[0]; bl[j2 * 2 + 0][1] = r[1];
                bl[j2 * 2 + 1][0] = r[2]; bl[j2 * 2 + 1][1] = r[3];
            }
            // ---- A fragments + MMA ----
            #pragma unroll
            for (int t = 0; t < 4; t++) {
                int mrow = wr * 64 + t * 16 + a_rl;
                int c = kk8 + a_cl;
                uint32_t off = (uint32_t)(mrow * 8 + (c ^ (mrow & 7))) * 16;
                uint32_t ah[4], al[4];
                ldsm_x4(ah, uAh + off);
                ldsm_x4(al, uAl + off);
                #pragma unroll
                for (int j = 0; j < 4; j++) mma_bf16(acc[t][j], ah, bh[j]);
                #pragma unroll
                for (int j = 0; j < 4; j++) mma_bf16(acc[t][j], ah, bl[j]);
                #pragma unroll
                for (int j = 0; j < 4; j++) mma_bf16(acc[t][j], al, bh[j]);
            }
        }
        __syncthreads();
    }

    // ---- epilogue: fp32 C ----
    float* Cp = C + (size_t)b * strC;
    #pragma unroll
    for (int t = 0; t < 4; t++) {
        int row = m0 + wr * 64 + t * 16 + (lane >> 2);
        #pragma unroll
        for (int j = 0; j < 4; j++) {
            int col = n0 + wc * 32 + j * 8 + ((lane & 3) << 1);
            *(float2*)(Cp + (size_t)row * ldc + col)       = make_float2(acc[t][j][0], acc[t][j][1]);
            *(float2*)(Cp + (size_t)(row + 8) * ldc + col) = make_float2(acc[t][j][2], acc[t][j][3]);
        }
    }
}

// ============================ softmax + split-convert ============================
__global__ __launch_bounds__(256)
void softmax_rows(const float* __restrict__ f,
                  __nv_bfloat16* __restrict__ p_hi, __nv_bfloat16* __restrict__ p_lo)
{
    const size_t rb = (size_t)blockIdx.x * NTOK;
    const float4* row = (const float4*)(f + rb);
    const int t = threadIdx.x;
    __shared__ float red[8];

    float4 v[4];
    float mx = -3.4e38f;
    #pragma unroll
    for (int i = 0; i < 4; i++) {
        v[i] = row[t + i * 256];
        mx = fmaxf(mx, fmaxf(fmaxf(v[i].x, v[i].y), fmaxf(v[i].z, v[i].w)));
    }
    #pragma unroll
    for (int o = 16; o; o >>= 1) mx = fmaxf(mx, __shfl_xor_sync(0xffffffffu, mx, o));
    if ((t & 31) == 0) red[t >> 5] = mx;
    __syncthreads();
    mx = red[0];
    #pragma unroll
    for (int i = 1; i < 8; i++) mx = fmaxf(mx, red[i]);

    float s = 0.0f;
    #pragma unroll
    for (int i = 0; i < 4; i++) {
        v[i].x = __expf(v[i].x - mx); v[i].y = __expf(v[i].y - mx);
        v[i].z = __expf(v[i].z - mx); v[i].w = __expf(v[i].w - mx);
        s += (v[i].x + v[i].y) + (v[i].z + v[i].w);
    }
    #pragma unroll
    for (int o = 16; o; o >>= 1) s += __shfl_xor_sync(0xffffffffu, s, o);
    __syncthreads();
    if ((t & 31) == 0) red[t >> 5] = s;
    __syncthreads();
    s = ((red[0] + red[1]) + (red[2] + red[3])) + ((red[4] + red[5]) + (red[6] + red[7]));
    float inv = 1.0f / s;

    #pragma unroll
    for (int i = 0; i < 4; i++) {
        int n = (t + i * 256) * 4;
        split_write4(p_hi + rb + n, p_lo + rb + n,
                     v[i].x * inv, v[i].y * inv, v[i].z * inv, v[i].w * inv);
    }
}

// ============================ wy GEMM (fp32 SIMT) ============================
// wy[c][n] = sum_d w_w[c,d] * y[n,d] + w_b[c]
__global__ __launch_bounds__(256, 2)
void wy_gemm(const float* __restrict__ W, const float* __restrict__ Y,
             const float* __restrict__ bias, float* __restrict__ C)
{
    __shared__ float As[8][132];
    __shared__ float Bs[8][132];
    const int b = blockIdx.z;
    const int m0 = blockIdx.y * 128;
    const int n0 = blockIdx.x * 128;
    const float* Bp = Y + (size_t)b * NTOK * DIM;
    float* Cp = C + (size_t)b * CHAN * NTOK;
    const int tid = threadIdx.x;
    const int tx = tid & 15, ty = tid >> 4;

    float acc[8][8] = {};
    for (int k0 = 0; k0 < DIM; k0 += 8) {
        { int r = tid >> 1; int q = (tid & 1) << 2;
          float4 v = *(const float4*)(W + (size_t)(m0 + r) * DIM + k0 + q);
          As[q + 0][r] = v.x; As[q + 1][r] = v.y; As[q + 2][r] = v.z; As[q + 3][r] = v.w; }
        { int r = tid >> 1; int q = (tid & 1) << 2;
          float4 v = *(const float4*)(Bp + (size_t)(n0 + r) * DIM + k0 + q);
          Bs[q + 0][r] = v.x; Bs[q + 1][r] = v.y; Bs[q + 2][r] = v.z; Bs[q + 3][r] = v.w; }
        __syncthreads();
        #pragma unroll
        for (int k = 0; k < 8; k++) {
            float a[8], bb[8];
            *(float4*)&a[0] = *(float4*)&As[k][ty * 4];
            *(float4*)&a[4] = *(float4*)&As[k][ty * 4 + 64];
            *(float4*)&bb[0] = *(float4*)&Bs[k][tx * 4];
            *(float4*)&bb[4] = *(float4*)&Bs[k][tx * 4 + 64];
            #pragma unroll
            for (int i = 0; i < 8; i++)
                #pragma unroll
                for (int j = 0; j < 8; j++)
                    acc[i][j] = fmaf(a[i], bb[j], acc[i][j]);
        }
        __syncthreads();
    }
    #pragma unroll
    for (int i = 0; i < 8; i++) {
        int m = m0 + ((i < 4) ? (ty * 4 + i) : (64 + ty * 4 + i - 4));
        float bv = bias[m];
        #pragma unroll
        for (int jg = 0; jg < 2; jg++) {
            int n = n0 + tx * 4 + jg * 64;
            float4 o;
            o.x = acc[i][jg * 4 + 0] + bv; o.y = acc[i][jg * 4 + 1] + bv;
            o.z = acc[i][jg * 4 + 2] + bv; o.w = acc[i][jg * 4 + 3] + bv;
            *(float4*)(Cp + (size_t)m * NTOK + n) = o;
        }
    }
}

// ============================ batchnorm ============================
__global__ __launch_bounds__(256)
void bn_stats(const float* __restrict__ wy)
{
    const int c = blockIdx.x;
    const int t = threadIdx.x;
    float s1 = 0.0f, s2 = 0.0f;
    #pragma unroll
    for (int b = 0; b < BATCH; b++) {
        const float* p = wy + ((size_t)(b * CHAN + c) << 12);
        for (int i = t; i < NTOK; i += 256) {
            float x = p[i];
            s1 += x; s2 += x * x;
        }
    }
    #pragma unroll
    for (int o = 16; o; o >>= 1) {
        s1 += __shfl_xor_sync(0xffffffffu, s1, o);
        s2 += __shfl_xor_sync(0xffffffffu, s2, o);
    }
    __shared__ float r1[8], r2[8];
    if ((t & 31) == 0) { r1[t >> 5] = s1; r2[t >> 5] = s2; }
    __syncthreads();
    if (t == 0) {
        s1 = 0.0f; s2 = 0.0f;
        #pragma unroll
        for (int i = 0; i < 8; i++) { s1 += r1[i]; s2 += r2[i]; }
        float mean = s1 * (1.0f / 16384.0f);
        float var  = s2 * (1.0f / 16384.0f) - mean * mean;
        g_mean[c] = mean;
        g_istd[c] = rsqrtf(var + 1e-5f);
    }
}

__global__ __launch_bounds__(256)
void bn_apply(const float* __restrict__ wy, const float* __restrict__ x,
              const float* __restrict__ gamma, const float* __restrict__ beta,
              float* __restrict__ out)
{
    int i4 = blockIdx.x * 256 + threadIdx.x;
    int c = (i4 >> 10) & (CHAN - 1);
    float is = g_istd[c];
    float ga = gamma[c] * is;
    float be = beta[c] - g_mean[c] * ga;
    float4 w = ((const float4*)wy)[i4];
    float4 xx = ((const float4*)x)[i4];
    float4 o;
    o.x = w.x * ga + be + xx.x;
    o.y = w.y * ga + be + xx.y;
    o.z = w.z * ga + be + xx.z;
    o.w = w.w * ga + be + xx.w;
    ((float4*)out)[i4] = o;
}

// ============================ launch ============================
extern "C" void kernel_launch(void* const* d_in, const int* in_sizes, int n_in,
                              void* d_out, int out_size)
{
    const float* x       = (const float*)d_in[0];
    const float* g_w     = (const float*)d_in[1];
    const float* g_b     = (const float*)d_in[2];
    const float* theta_w = (const float*)d_in[3];
    const float* theta_b = (const float*)d_in[4];
    const float* phi_w   = (const float*)d_in[5];
    const float* phi_b   = (const float*)d_in[6];
    const float* w_w     = (const float*)d_in[7];
    const float* w_b     = (const float*)d_in[8];
    const float* gamma   = (const float*)d_in[9];
    const float* beta    = (const float*)d_in[10];
    float* out = (float*)d_out;

    float *f, *y, *wy;
    __nv_bfloat16 *thh, *thl, *phh, *phl, *ghh, *ghl, *p_hi, *p_lo;
    cudaGetSymbolAddress((void**)&f,    g_f);
    cudaGetSymbolAddress((void**)&y,    g_y);
    cudaGetSymbolAddress((void**)&wy,   g_wy);
    cudaGetSymbolAddress((void**)&thh,  g_th_hi);
    cudaGetSymbolAddress((void**)&thl,  g_th_lo);
    cudaGetSymbolAddress((void**)&phh,  g_ph_hi);
    cudaGetSymbolAddress((void**)&phl,  g_ph_lo);
    cudaGetSymbolAddress((void**)&ghh,  g_g_hi);
    cudaGetSymbolAddress((void**)&ghl,  g_g_lo);
    cudaGetSymbolAddress((void**)&p_hi, g_p_hi);
    cudaGetSymbolAddress((void**)&p_lo, g_p_lo);

    cudaFuncSetAttribute(mma_gemm_tt, cudaFuncAttributeMaxDynamicSharedMemorySize, GT_SMEM);

    // projections
    proj_nd<<<dim3(32, 1, BATCH), 256>>>(x, theta_w, theta_b, thh, thl);
    proj_nd<<<dim3(32, 1, BATCH), 256>>>(x, phi_w,   phi_b,   phh, phl);
    proj_dn<<<dim3(32, 1, BATCH), 256>>>(x, g_w,     g_b,     ghh, ghl);

    // logits: f[n,m] = theta[n,:] . phi[m,:]
    mma_gemm_tt<<<dim3(32, 32, BATCH), 256, GT_SMEM>>>(
        thh, thl, phh, phl, f,
        DIM, DIM, NTOK, DIM / 64,
        (size_t)NTOK * DIM, (size_t)NTOK * DIM, (size_t)NTOK * NTOK);

    // softmax + bf16 split of P
    softmax_rows<<<BATCH * NTOK, 256>>>(f, p_hi, p_lo);

    // y[n,d] = P[n,:] . g[d,:]
    mma_gemm_tt<<<dim3(1, 32, BATCH), 256, GT_SMEM>>>(
        p_hi, p_lo, ghh, ghl, y,
        NTOK, NTOK, DIM, NTOK / 64,
        (size_t)NTOK * NTOK, (size_t)DIM * NTOK, (size_t)NTOK * DIM);

    // back-projection
    wy_gemm<<<dim3(32, 2, BATCH), 256>>>(w_w, y, w_b, wy);

    // batchnorm + residual
    bn_stats<<<CHAN, 256>>>(wy);
    bn_apply<<<(BATCH * CHAN * NTOK / 4) / 256, 256>>>(wy, x, gamma, beta, out);
}

// round 4
// speedup vs baseline: 2.2055x; 1.2100x over previous
#include <cuda_runtime.h>
#include <cuda_bf16.h>
#include <cstdint>
#include <math.h>

#define BATCH 4
#define CHAN  256
#define DIM   128
#define NTOK  4096

// ============================ scratch ============================
__device__ float g_f[(size_t)BATCH * NTOK * NTOK];     // logits (fp32)
__device__ __nv_bfloat16 g_p_hi[(size_t)BATCH * NTOK * NTOK];
__device__ __nv_bfloat16 g_p_lo[(size_t)BATCH * NTOK * NTOK];
__device__ __nv_bfloat16 g_th_hi[BATCH * NTOK * DIM];  // theta token-major [n,d]
__device__ __nv_bfloat16 g_th_lo[BATCH * NTOK * DIM];
__device__ __nv_bfloat16 g_ph_hi[BATCH * NTOK * DIM];  // phi token-major [m,d]
__device__ __nv_bfloat16 g_ph_lo[BATCH * NTOK * DIM];
__device__ __nv_bfloat16 g_g_hi[BATCH * DIM * NTOK];   // g d-major [d,m]
__device__ __nv_bfloat16 g_g_lo[BATCH * DIM * NTOK];
__device__ __nv_bfloat16 g_y_hi[BATCH * NTOK * DIM];   // y token-major [n,d]
__device__ __nv_bfloat16 g_y_lo[BATCH * NTOK * DIM];
__device__ __nv_bfloat16 g_ww_hi[CHAN * DIM];
__device__ __nv_bfloat16 g_ww_lo[CHAN * DIM];
__device__ float g_wy[BATCH * CHAN * NTOK];
__device__ float g_mean[CHAN];
__device__ float g_istd[CHAN];

// ============================ helpers ============================
__device__ __forceinline__ uint32_t smem_to_u32(const void* p) {
    uint32_t a;
    asm("{ .reg .u64 t; cvta.to.shared.u64 t, %1; cvt.u32.u64 %0, t; }" : "=r"(a) : "l"(p));
    return a;
}
__device__ __forceinline__ void cpa16(uint32_t saddr, const void* g) {
    asm volatile("cp.async.cg.shared.global [%0], [%1], 16;" :: "r"(saddr), "l"(g));
}
__device__ __forceinline__ void cpa_commit() {
    asm volatile("cp.async.commit_group;" ::: "memory");
}
__device__ __forceinline__ void cpa_wait1() {
    asm volatile("cp.async.wait_group 1;" ::: "memory");
}
__device__ __forceinline__ void ldsm_x4(uint32_t* r, uint32_t addr) {
    asm volatile("ldmatrix.sync.aligned.m8n8.x4.shared.b16 {%0,%1,%2,%3}, [%4];"
                 : "=r"(r[0]), "=r"(r[1]), "=r"(r[2]), "=r"(r[3]) : "r"(addr));
}
__device__ __forceinline__ void mma_bf16(float* c, const uint32_t* a, const uint32_t* b) {
    asm volatile("mma.sync.aligned.m16n8k16.row.col.f32.bf16.bf16.f32 "
                 "{%0,%1,%2,%3}, {%4,%5,%6,%7}, {%8,%9}, {%0,%1,%2,%3};"
                 : "+f"(c[0]), "+f"(c[1]), "+f"(c[2]), "+f"(c[3])
                 : "r"(a[0]), "r"(a[1]), "r"(a[2]), "r"(a[3]), "r"(b[0]), "r"(b[1]));
}
__device__ __forceinline__ void split_write4(__nv_bfloat16* hi, __nv_bfloat16* lo,
                                             float a, float b, float c, float d) {
    __nv_bfloat16 h0 = __float2bfloat16_rn(a), h1 = __float2bfloat16_rn(b);
    __nv_bfloat16 h2 = __float2bfloat16_rn(c), h3 = __float2bfloat16_rn(d);
    __nv_bfloat16 l0 = __float2bfloat16_rn(a - __bfloat162float(h0));
    __nv_bfloat16 l1 = __float2bfloat16_rn(b - __bfloat162float(h1));
    __nv_bfloat16 l2 = __float2bfloat16_rn(c - __bfloat162float(h2));
    __nv_bfloat16 l3 = __float2bfloat16_rn(d - __bfloat162float(h3));
    *(__nv_bfloat162*)(hi + 0) = __nv_bfloat162(h0, h1);
    *(__nv_bfloat162*)(hi + 2) = __nv_bfloat162(h2, h3);
    *(__nv_bfloat162*)(lo + 0) = __nv_bfloat162(l0, l1);
    *(__nv_bfloat162*)(lo + 2) = __nv_bfloat162(l2, l3);
}
__device__ __forceinline__ void split_write2(__nv_bfloat16* hi, __nv_bfloat16* lo,
                                             float a, float b) {
    __nv_bfloat16 h0 = __float2bfloat16_rn(a), h1 = __float2bfloat16_rn(b);
    __nv_bfloat16 l0 = __float2bfloat16_rn(a - __bfloat162float(h0));
    __nv_bfloat16 l1 = __float2bfloat16_rn(b - __bfloat162float(h1));
    *(__nv_bfloat162*)hi = __nv_bfloat162(h0, h1);
    *(__nv_bfloat162*)lo = __nv_bfloat162(l0, l1);
}

// ============================ unified pipelined mma.sync GEMM ============================
// C[m,n] = sum_k A[m,k]*B[n,k]  (both row-major over K), split bf16 3-pass.
// CTA tile BM x 128, K-chunk 32, 2-stage cp.async pipeline, 8 warps (2 x 4).
// SMEM rows: 32 bf16 = 64B stored with 80B stride -> conflict-free LDSM, no swizzle.
// EPI: 0 = fp32 C, 1 = split bf16 (Ch/Cl), 2 = fp32 C + bias[m].
template<int BM, int EPI>
__global__ __launch_bounds__(256, 2)
void mma_tt(const __nv_bfloat16* __restrict__ Ah, const __nv_bfloat16* __restrict__ Al,
            const __nv_bfloat16* __restrict__ Bh, const __nv_bfloat16* __restrict__ Bl,
            float* __restrict__ C, __nv_bfloat16* __restrict__ Ch, __nv_bfloat16* __restrict__ Cl,
            const float* __restrict__ bias,
            int lda, int ldb, int ldc, int kchunks,
            size_t strA, size_t strB, size_t strC)
{
    constexpr int TM = BM / 32;             // m16 frags per warp
    constexpr int A_BYTES = BM * 80;
    constexpr int B_BYTES = 128 * 80;
    constexpr int SS = 2 * A_BYTES + 2 * B_BYTES;

    extern __shared__ char smem[];
    const uint32_t sb = smem_to_u32(smem);

    const int tid = threadIdx.x;
    const int lane = tid & 31, wid = tid >> 5;
    const int wr = wid >> 2;                // 0..1
    const int wc = wid & 3;                 // 0..3
    const int b  = blockIdx.z;
    const int m0 = blockIdx.y * BM;
    const int n0 = blockIdx.x * 128;

    const __nv_bfloat16* pAh = Ah + (size_t)b * strA + (size_t)m0 * lda;
    const __nv_bfloat16* pAl = Al + (size_t)b * strA + (size_t)m0 * lda;
    const __nv_bfloat16* pBh = Bh + (size_t)b * strB + (size_t)n0 * ldb;
    const __nv_bfloat16* pBl = Bl + (size_t)b * strB + (size_t)n0 * ldb;

    float acc[TM][4][4] = {};

    const int a_rl = ((lane >> 3) & 1) * 8 + (lane & 7);
    const int a_cl = lane >> 4;
    const int b_rl = (lane >> 4) * 8 + (lane & 7);
    const int b_cl = (lane >> 3) & 1;

    auto load_stage = [&](int s, int kc) {
        const uint32_t st = sb + s * SS;
        const int k0 = kc * 32;
        #pragma unroll
        for (int i = tid; i < BM * 4; i += 256) {
            int r = i >> 2, c = i & 3;
            uint32_t so = st + r * 80 + c * 16;
            size_t g = (size_t)r * lda + k0 + c * 8;
            cpa16(so,           pAh + g);
            cpa16(so + A_BYTES, pAl + g);
        }
        #pragma unroll
        for (int i = tid; i < 512; i += 256) {
            int r = i >> 2, c = i & 3;
            uint32_t so = st + 2 * A_BYTES + r * 80 + c * 16;
            size_t g = (size_t)r * ldb + k0 + c * 8;
            cpa16(so,           pBh + g);
            cpa16(so + B_BYTES, pBl + g);
        }
    };

    // prologue: fill both stages
    load_stage(0, 0); cpa_commit();
    if (kchunks > 1) load_stage(1, 1);
    cpa_commit();

    for (int kc = 0; kc < kchunks; kc++) {
        cpa_wait1();
        __syncthreads();
        const uint32_t st = sb + (kc & 1) * SS;
        const uint32_t uAh = st, uAl = st + A_BYTES;
        const uint32_t uBh = st + 2 * A_BYTES, uBl = uBh + B_BYTES;

        #pragma unroll
        for (int ks = 0; ks < 2; ks++) {
            const int kk8 = ks * 2;
            uint32_t bh[4][2], bl[4][2];
            #pragma unroll
            for (int j2 = 0; j2 < 2; j2++) {
                int nrow = wc * 32 + j2 * 16 + b_rl;
                uint32_t off = (uint32_t)(nrow * 80 + (kk8 + b_cl) * 16);
                uint32_t r[4];
                ldsm_x4(r, uBh + off);
                bh[j2 * 2 + 0][0] = r[0]; bh[j2 * 2 + 0][1] = r[1];
                bh[j2 * 2 + 1][0] = r[2]; bh[j2 * 2 + 1][1] = r[3];
                ldsm_x4(r, uBl + off);
                bl[j2 * 2 + 0][0] = r[0]; bl[j2 * 2 + 0][1] = r[1];
                bl[j2 * 2 + 1][0] = r[2]; bl[j2 * 2 + 1][1] = r[3];
            }
            #pragma unroll
            for (int t = 0; t < TM; t++) {
                int mrow = wr * (BM / 2) + t * 16 + a_rl;
                uint32_t off = (uint32_t)(mrow * 80 + (kk8 + a_cl) * 16);
                uint32_t ah[4], al[4];
                ldsm_x4(ah, uAh + off);
                ldsm_x4(al, uAl + off);
                #pragma unroll
                for (int j = 0; j < 4; j++) mma_bf16(acc[t][j], ah, bh[j]);
                #pragma unroll
                for (int j = 0; j < 4; j++) mma_bf16(acc[t][j], ah, bl[j]);
                #pragma unroll
                for (int j = 0; j < 4; j++) mma_bf16(acc[t][j], al, bh[j]);
            }
        }
        __syncthreads();
        int nk = kc + 2;
        if (nk < kchunks) load_stage(kc & 1, nk);
        cpa_commit();
    }

    // ---- epilogue ----
    #pragma unroll
    for (int t = 0; t < TM; t++) {
        int row = m0 + wr * (BM / 2) + t * 16 + (lane >> 2);
        #pragma unroll
        for (int j = 0; j < 4; j++) {
            int col = n0 + wc * 32 + j * 8 + ((lane & 3) << 1);
            if (EPI == 1) {
                __nv_bfloat16* ph = Ch + (size_t)b * strC;
                __nv_bfloat16* pl = Cl + (size_t)b * strC;
                split_write2(ph + (size_t)row * ldc + col, pl + (size_t)row * ldc + col,
                             acc[t][j][0], acc[t][j][1]);
                split_write2(ph + (size_t)(row + 8) * ldc + col, pl + (size_t)(row + 8) * ldc + col,
                             acc[t][j][2], acc[t][j][3]);
            } else {
                float* Cp = C + (size_t)b * strC;
                float b0 = 0.0f, b1 = 0.0f;
                if (EPI == 2) { b0 = bias[row]; b1 = bias[row + 8]; }
                *(float2*)(Cp + (size_t)row * ldc + col) =
                    make_float2(acc[t][j][0] + b0, acc[t][j][1] + b0);
                *(float2*)(Cp + (size_t)(row + 8) * ldc + col) =
                    make_float2(acc[t][j][2] + b1, acc[t][j][3] + b1);
            }
        }
    }
}

// ============================ projections (fp32 SIMT) ============================
__global__ __launch_bounds__(256, 2)
void proj_nd(const float* __restrict__ x, const float* __restrict__ W,
             const float* __restrict__ bias,
             __nv_bfloat16* __restrict__ out_hi, __nv_bfloat16* __restrict__ out_lo)
{
    __shared__ float As[8][132];
    __shared__ float Bs[8][132];
    const int b = blockIdx.z;
    const int m0 = blockIdx.x * 128;
    const float* A = x + (size_t)b * CHAN * NTOK;
    const int tid = threadIdx.x;
    const int tx = tid & 15, ty = tid >> 4;

    float acc[8][8] = {};
    for (int k0 = 0; k0 < CHAN; k0 += 8) {
        { int r = tid >> 5; int c = (tid & 31) << 2;
          float4 v = *(const float4*)(A + (size_t)(k0 + r) * NTOK + m0 + c);
          *(float4*)&As[r][c] = v; }
        { int r = tid >> 1; int q = (tid & 1) << 2;
          float4 v = *(const float4*)(W + (size_t)r * CHAN + k0 + q);
          Bs[q + 0][r] = v.x; Bs[q + 1][r] = v.y; Bs[q + 2][r] = v.z; Bs[q + 3][r] = v.w; }
        __syncthreads();
        #pragma unroll
        for (int k = 0; k < 8; k++) {
            float a[8], bb[8];
            *(float4*)&a[0] = *(float4*)&As[k][ty * 4];
            *(float4*)&a[4] = *(float4*)&As[k][ty * 4 + 64];
            *(float4*)&bb[0] = *(float4*)&Bs[k][tx * 4];
            *(float4*)&bb[4] = *(float4*)&Bs[k][tx * 4 + 64];
            #pragma unroll
            for (int i = 0; i < 8; i++)
                #pragma unroll
                for (int j = 0; j < 8; j++)
                    acc[i][j] = fmaf(a[i], bb[j], acc[i][j]);
        }
        __syncthreads();
    }
    float bv[8];
    #pragma unroll
    for (int jg = 0; jg < 2; jg++)
        #pragma unroll
        for (int j = 0; j < 4; j++) bv[jg * 4 + j] = bias[tx * 4 + jg * 64 + j];
    #pragma unroll
    for (int i = 0; i < 8; i++) {
        int m = m0 + ((i < 4) ? (ty * 4 + i) : (64 + ty * 4 + i - 4));
        __nv_bfloat16* oh = out_hi + ((size_t)b * NTOK + m) * DIM;
        __nv_bfloat16* ol = out_lo + ((size_t)b * NTOK + m) * DIM;
        #pragma unroll
        for (int jg = 0; jg < 2; jg++) {
            int n = tx * 4 + jg * 64;
            split_write4(oh + n, ol + n,
                         acc[i][jg * 4 + 0] + bv[jg * 4 + 0],
                         acc[i][jg * 4 + 1] + bv[jg * 4 + 1],
                         acc[i][jg * 4 + 2] + bv[jg * 4 + 2],
                         acc[i][jg * 4 + 3] + bv[jg * 4 + 3]);
        }
    }
}

__global__ __launch_bounds__(256, 2)
void proj_dn(const float* __restrict__ x, const float* __restrict__ W,
             const float* __restrict__ bias,
             __nv_bfloat16* __restrict__ out_hi, __nv_bfloat16* __restrict__ out_lo)
{
    __shared__ float As[8][132];
    __shared__ float Bs[8][132];
    const int b = blockIdx.z;
    const int n0 = blockIdx.x * 128;
    const float* B = x + (size_t)b * CHAN * NTOK;
    const int tid = threadIdx.x;
    const int tx = tid & 15, ty = tid >> 4;

    float acc[8][8] = {};
    for (int k0 = 0; k0 < CHAN; k0 += 8) {
        { int r = tid >> 1; int q = (tid & 1) << 2;
          float4 v = *(const float4*)(W + (size_t)r * CHAN + k0 + q);
          As[q + 0][r] = v.x; As[q + 1][r] = v.y; As[q + 2][r] = v.z; As[q + 3][r] = v.w; }
        { int r = tid >> 5; int c = (tid & 31) << 2;
          float4 v = *(const float4*)(B + (size_t)(k0 + r) * NTOK + n0 + c);
          *(float4*)&Bs[r][c] = v; }
        __syncthreads();
        #pragma unroll
        for (int k = 0; k < 8; k++) {
            float a[8], bb[8];
            *(float4*)&a[0] = *(float4*)&As[k][ty * 4];
            *(float4*)&a[4] = *(float4*)&As[k][ty * 4 + 64];
            *(float4*)&bb[0] = *(float4*)&Bs[k][tx * 4];
            *(float4*)&bb[4] = *(float4*)&Bs[k][tx * 4 + 64];
            #pragma unroll
            for (int i = 0; i < 8; i++)
                #pragma unroll
                for (int j = 0; j < 8; j++)
                    acc[i][j] = fmaf(a[i], bb[j], acc[i][j]);
        }
        __syncthreads();
    }
    #pragma unroll
    for (int i = 0; i < 8; i++) {
        int m = (i < 4) ? (ty * 4 + i) : (64 + ty * 4 + i - 4);
        float bvm = bias[m];
        __nv_bfloat16* oh = out_hi + ((size_t)b * DIM + m) * NTOK;
        __nv_bfloat16* ol = out_lo + ((size_t)b * DIM + m) * NTOK;
        #pragma unroll
        for (int jg = 0; jg < 2; jg++) {
            int n = n0 + tx * 4 + jg * 64;
            split_write4(oh + n, ol + n,
                         acc[i][jg * 4 + 0] + bvm, acc[i][jg * 4 + 1] + bvm,
                         acc[i][jg * 4 + 2] + bvm, acc[i][jg * 4 + 3] + bvm);
        }
    }
}

// ============================ w_w split (tiny) ============================
__global__ __launch_bounds__(256)
void w_split(const float* __restrict__ w,
             __nv_bfloat16* __restrict__ hi, __nv_bfloat16* __restrict__ lo)
{
    int i = (blockIdx.x * 256 + threadIdx.x) * 4;
    float4 v = *(const float4*)(w + i);
    split_write4(hi + i, lo + i, v.x, v.y, v.z, v.w);
}

// ============================ softmax + split-convert ============================
__global__ __launch_bounds__(256)
void softmax_rows(const float* __restrict__ f,
                  __nv_bfloat16* __restrict__ p_hi, __nv_bfloat16* __restrict__ p_lo)
{
    const size_t rb = (size_t)blockIdx.x * NTOK;
    const float4* row = (const float4*)(f + rb);
    const int t = threadIdx.x;
    __shared__ float red[8];

    float4 v[4];
    float mx = -3.4e38f;
    #pragma unroll
    for (int i = 0; i < 4; i++) {
        v[i] = row[t + i * 256];
        mx = fmaxf(mx, fmaxf(fmaxf(v[i].x, v[i].y), fmaxf(v[i].z, v[i].w)));
    }
    #pragma unroll
    for (int o = 16; o; o >>= 1) mx = fmaxf(mx, __shfl_xor_sync(0xffffffffu, mx, o));
    if ((t & 31) == 0) red[t >> 5] = mx;
    __syncthreads();
    mx = red[0];
    #pragma unroll
    for (int i = 1; i < 8; i++) mx = fmaxf(mx, red[i]);

    float s = 0.0f;
    #pragma unroll
    for (int i = 0; i < 4; i++) {
        v[i].x = __expf(v[i].x - mx); v[i].y = __expf(v[i].y - mx);
        v[i].z = __expf(v[i].z - mx); v[i].w = __expf(v[i].w - mx);
        s += (v[i].x + v[i].y) + (v[i].z + v[i].w);
    }
    #pragma unroll
    for (int o = 16; o; o >>= 1) s += __shfl_xor_sync(0xffffffffu, s, o);
    __syncthreads();
    if ((t & 31) == 0) red[t >> 5] = s;
    __syncthreads();
    s = ((red[0] + red[1]) + (red[2] + red[3])) + ((red[4] + red[5]) + (red[6] + red[7]));
    float inv = 1.0f / s;

    #pragma unroll
    for (int i = 0; i < 4; i++) {
        int n = (t + i * 256) * 4;
        split_write4(p_hi + rb + n, p_lo + rb + n,
                     v[i].x * inv, v[i].y * inv, v[i].z * inv, v[i].w * inv);
    }
}

// ============================ batchnorm ============================
__global__ __launch_bounds__(256)
void bn_stats(const float* __restrict__ wy)
{
    const int c = blockIdx.x;
    const int t = threadIdx.x;
    float s1 = 0.0f, s2 = 0.0f;
    #pragma unroll
    for (int b = 0; b < BATCH; b++) {
        const float* p = wy + ((size_t)(b * CHAN + c) << 12);
        for (int i = t; i < NTOK; i += 256) {
            float x = p[i];
            s1 += x; s2 += x * x;
        }
    }
    #pragma unroll
    for (int o = 16; o; o >>= 1) {
        s1 += __shfl_xor_sync(0xffffffffu, s1, o);
        s2 += __shfl_xor_sync(0xffffffffu, s2, o);
    }
    __shared__ float r1[8], r2[8];
    if ((t & 31) == 0) { r1[t >> 5] = s1; r2[t >> 5] = s2; }
    __syncthreads();
    if (t == 0) {
        s1 = 0.0f; s2 = 0.0f;
        #pragma unroll
        for (int i = 0; i < 8; i++) { s1 += r1[i]; s2 += r2[i]; }
        float mean = s1 * (1.0f / 16384.0f);
        float var  = s2 * (1.0f / 16384.0f) - mean * mean;
        g_mean[c] = mean;
        g_istd[c] = rsqrtf(var + 1e-5f);
    }
}

__global__ __launch_bounds__(256)
void bn_apply(const float* __restrict__ wy, const float* __restrict__ x,
              const float* __restrict__ gamma, const float* __restrict__ beta,
              float* __restrict__ out)
{
    int i4 = blockIdx.x * 256 + threadIdx.x;
    int c = (i4 >> 10) & (CHAN - 1);
    float is = g_istd[c];
    float ga = gamma[c] * is;
    float be = beta[c] - g_mean[c] * ga;
    float4 w = ((const float4*)wy)[i4];
    float4 xx = ((const float4*)x)[i4];
    float4 o;
    o.x = w.x * ga + be + xx.x;
    o.y = w.y * ga + be + xx.y;
    o.z = w.z * ga + be + xx.z;
    o.w = w.w * ga + be + xx.w;
    ((float4*)out)[i4] = o;
}

// ============================ launch ============================
#define SMEM_128 (2 * (2 * 128 * 80 + 2 * 128 * 80))   // 81920
#define SMEM_64  (2 * (2 * 64 * 80 + 2 * 128 * 80))    // 61440

extern "C" void kernel_launch(void* const* d_in, const int* in_sizes, int n_in,
                              void* d_out, int out_size)
{
    const float* x       = (const float*)d_in[0];
    const float* g_w     = (const float*)d_in[1];
    const float* g_b     = (const float*)d_in[2];
    const float* theta_w = (const float*)d_in[3];
    const float* theta_b = (const float*)d_in[4];
    const float* phi_w   = (const float*)d_in[5];
    const float* phi_b   = (const float*)d_in[6];
    const float* w_w     = (const float*)d_in[7];
    const float* w_b     = (const float*)d_in[8];
    const float* gamma   = (const float*)d_in[9];
    const float* beta    = (const float*)d_in[10];
    float* out = (float*)d_out;

    float *f, *wy;
    __nv_bfloat16 *thh, *thl, *phh, *phl, *ghh, *ghl, *p_hi, *p_lo, *y_hi, *y_lo, *wwh, *wwl;
    cudaGetSymbolAddress((void**)&f,    g_f);
    cudaGetSymbolAddress((void**)&wy,   g_wy);
    cudaGetSymbolAddress((void**)&thh,  g_th_hi);
    cudaGetSymbolAddress((void**)&thl,  g_th_lo);
    cudaGetSymbolAddress((void**)&phh,  g_ph_hi);
    cudaGetSymbolAddress((void**)&phl,  g_ph_lo);
    cudaGetSymbolAddress((void**)&ghh,  g_g_hi);
    cudaGetSymbolAddress((void**)&ghl,  g_g_lo);
    cudaGetSymbolAddress((void**)&p_hi, g_p_hi);
    cudaGetSymbolAddress((void**)&p_lo, g_p_lo);
    cudaGetSymbolAddress((void**)&y_hi, g_y_hi);
    cudaGetSymbolAddress((void**)&y_lo, g_y_lo);
    cudaGetSymbolAddress((void**)&wwh,  g_ww_hi);
    cudaGetSymbolAddress((void**)&wwl,  g_ww_lo);

    cudaFuncSetAttribute(mma_tt<128, 0>, cudaFuncAttributeMaxDynamicSharedMemorySize, SMEM_128);
    cudaFuncSetAttribute(mma_tt<64, 1>,  cudaFuncAttributeMaxDynamicSharedMemorySize, SMEM_64);
    cudaFuncSetAttribute(mma_tt<128, 2>, cudaFuncAttributeMaxDynamicSharedMemorySize, SMEM_128);

    // projections + weight split
    proj_nd<<<dim3(32, 1, BATCH), 256>>>(x, theta_w, theta_b, thh, thl);
    proj_nd<<<dim3(32, 1, BATCH), 256>>>(x, phi_w,   phi_b,   phh, phl);
    proj_dn<<<dim3(32, 1, BATCH), 256>>>(x, g_w,     g_b,     ghh, ghl);
    w_split<<<CHAN * DIM / 1024, 256>>>(w_w, wwh, wwl);

    // logits: f[n,m] = theta[n,:] . phi[m,:]
    mma_tt<128, 0><<<dim3(32, 32, BATCH), 256, SMEM_128>>>(
        thh, thl, phh, phl, f, nullptr, nullptr, nullptr,
        DIM, DIM, NTOK, DIM / 32,
        (size_t)NTOK * DIM, (size_t)NTOK * DIM, (size_t)NTOK * NTOK);

    // softmax + bf16 split of P
    softmax_rows<<<BATCH * NTOK, 256>>>(f, p_hi, p_lo);

    // y[n,d] = P[n,:] . g[d,:]  -> bf16 hi/lo
    mma_tt<64, 1><<<dim3(1, 64, BATCH), 256, SMEM_64>>>(
        p_hi, p_lo, ghh, ghl, nullptr, y_hi, y_lo, nullptr,
        NTOK, NTOK, DIM, NTOK / 32,
        (size_t)NTOK * NTOK, (size_t)DIM * NTOK, (size_t)NTOK * DIM);

    // wy[c,n] = w_w[c,:] . y[n,:] + w_b[c]
    mma_tt<128, 2><<<dim3(32, 2, BATCH), 256, SMEM_128>>>(
        wwh, wwl, y_hi, y_lo, wy, nullptr, nullptr, w_b,
        DIM, DIM, NTOK, DIM / 32,
        0, (size_t)NTOK * DIM, (size_t)CHAN * NTOK);

    // batchnorm + residual
    bn_stats<<<CHAN, 256>>>(wy);
    bn_apply<<<(BATCH * CHAN * NTOK / 4) / 256, 256>>>(wy, x, gamma, beta, out);
}

// round 5
// speedup vs baseline: 2.3060x; 1.0456x over previous
#include <cuda_runtime.h>
#include <cuda_bf16.h>
#include <cstdint>
#include <math.h>

#define BATCH 4
#define CHAN  256
#define DIM   128
#define NTOK  4096

// ============================ scratch ============================
__device__ __nv_bfloat16 g_p_hi[(size_t)BATCH * NTOK * NTOK];   // unnormalized exp(f)
__device__ __nv_bfloat16 g_p_lo[(size_t)BATCH * NTOK * NTOK];
__device__ __nv_bfloat16 g_th_hi[BATCH * NTOK * DIM];  // theta token-major [n,d]
__device__ __nv_bfloat16 g_th_lo[BATCH * NTOK * DIM];
__device__ __nv_bfloat16 g_ph_hi[BATCH * NTOK * DIM];  // phi token-major [m,d]
__device__ __nv_bfloat16 g_ph_lo[BATCH * NTOK * DIM];
__device__ __nv_bfloat16 g_g_hi[BATCH * DIM * NTOK];   // g d-major [d,m]
__device__ __nv_bfloat16 g_g_lo[BATCH * DIM * NTOK];
__device__ __nv_bfloat16 g_y_hi[BATCH * NTOK * DIM];   // y token-major [n,d] (normalized)
__device__ __nv_bfloat16 g_y_lo[BATCH * NTOK * DIM];
__device__ __nv_bfloat16 g_ww_hi[CHAN * DIM];
__device__ __nv_bfloat16 g_ww_lo[CHAN * DIM];
__device__ float g_wy[BATCH * CHAN * NTOK];
__device__ float g_mean[CHAN];
__device__ float g_istd[CHAN];

// ============================ helpers ============================
__device__ __forceinline__ uint32_t smem_to_u32(const void* p) {
    uint32_t a;
    asm("{ .reg .u64 t; cvta.to.shared.u64 t, %1; cvt.u32.u64 %0, t; }" : "=r"(a) : "l"(p));
    return a;
}
__device__ __forceinline__ void cpa16(uint32_t saddr, const void* g) {
    asm volatile("cp.async.cg.shared.global [%0], [%1], 16;" :: "r"(saddr), "l"(g));
}
__device__ __forceinline__ void cpa_commit() {
    asm volatile("cp.async.commit_group;" ::: "memory");
}
__device__ __forceinline__ void cpa_wait1() {
    asm volatile("cp.async.wait_group 1;" ::: "memory");
}
__device__ __forceinline__ void ldsm_x4(uint32_t* r, uint32_t addr) {
    asm volatile("ldmatrix.sync.aligned.m8n8.x4.shared.b16 {%0,%1,%2,%3}, [%4];"
                 : "=r"(r[0]), "=r"(r[1]), "=r"(r[2]), "=r"(r[3]) : "r"(addr));
}
__device__ __forceinline__ void mma_bf16(float* c, const uint32_t* a, const uint32_t* b) {
    asm volatile("mma.sync.aligned.m16n8k16.row.col.f32.bf16.bf16.f32 "
                 "{%0,%1,%2,%3}, {%4,%5,%6,%7}, {%8,%9}, {%0,%1,%2,%3};"
                 : "+f"(c[0]), "+f"(c[1]), "+f"(c[2]), "+f"(c[3])
                 : "r"(a[0]), "r"(a[1]), "r"(a[2]), "r"(a[3]), "r"(b[0]), "r"(b[1]));
}
__device__ __forceinline__ float bf2sum(uint32_t u) {
    __nv_bfloat162 v = *reinterpret_cast<__nv_bfloat162*>(&u);
    float2 f = __bfloat1622float2(v);
    return f.x + f.y;
}
__device__ __forceinline__ void split_write4(__nv_bfloat16* hi, __nv_bfloat16* lo,
                                             float a, float b, float c, float d) {
    __nv_bfloat16 h0 = __float2bfloat16_rn(a), h1 = __float2bfloat16_rn(b);
    __nv_bfloat16 h2 = __float2bfloat16_rn(c), h3 = __float2bfloat16_rn(d);
    __nv_bfloat16 l0 = __float2bfloat16_rn(a - __bfloat162float(h0));
    __nv_bfloat16 l1 = __float2bfloat16_rn(b - __bfloat162float(h1));
    __nv_bfloat16 l2 = __float2bfloat16_rn(c - __bfloat162float(h2));
    __nv_bfloat16 l3 = __float2bfloat16_rn(d - __bfloat162float(h3));
    *(__nv_bfloat162*)(hi + 0) = __nv_bfloat162(h0, h1);
    *(__nv_bfloat162*)(hi + 2) = __nv_bfloat162(h2, h3);
    *(__nv_bfloat162*)(lo + 0) = __nv_bfloat162(l0, l1);
    *(__nv_bfloat162*)(lo + 2) = __nv_bfloat162(l2, l3);
}
__device__ __forceinline__ void split_write2(__nv_bfloat16* hi, __nv_bfloat16* lo,
                                             float a, float b) {
    __nv_bfloat16 h0 = __float2bfloat16_rn(a), h1 = __float2bfloat16_rn(b);
    __nv_bfloat16 l0 = __float2bfloat16_rn(a - __bfloat162float(h0));
    __nv_bfloat16 l1 = __float2bfloat16_rn(b - __bfloat162float(h1));
    *(__nv_bfloat162*)hi = __nv_bfloat162(h0, h1);
    *(__nv_bfloat162*)lo = __nv_bfloat162(l0, l1);
}

// ============================ unified pipelined mma.sync GEMM ============================
// C[m,n] = sum_k A[m,k]*B[n,k] (both row-major over K), split bf16 3-pass.
// CTA tile BM x 128, K-chunk 32, 2-stage cp.async pipeline, 8 warps (2 x 4).
// SMEM rows: 32 bf16 = 64B stored with 80B stride -> conflict-free LDSM, no swizzle.
// EPI: 1 = split bf16 (optionally normalized by row sum of A when NORM),
//      2 = fp32 C + bias[m],  3 = exp(acc) -> split bf16.
// NORM: accumulate per-row sums of (Ah+Al) from A fragments; epilogue divides by them.
template<int BM, int EPI, bool NORM>
__global__ __launch_bounds__(256, 2)
void mma_tt(const __nv_bfloat16* __restrict__ Ah, const __nv_bfloat16* __restrict__ Al,
            const __nv_bfloat16* __restrict__ Bh, const __nv_bfloat16* __restrict__ Bl,
            float* __restrict__ C, __nv_bfloat16* __restrict__ Ch, __nv_bfloat16* __restrict__ Cl,
            const float* __restrict__ bias,
            int lda, int ldb, int ldc, int kchunks,
            size_t strA, size_t strB, size_t strC)
{
    constexpr int TM = BM / 32;             // m16 frags per warp
    constexpr int A_BYTES = BM * 80;
    constexpr int B_BYTES = 128 * 80;
    constexpr int SS = 2 * A_BYTES + 2 * B_BYTES;

    extern __shared__ char smem[];
    const uint32_t sb = smem_to_u32(smem);

    const int tid = threadIdx.x;
    const int lane = tid & 31, wid = tid >> 5;
    const int wr = wid >> 2;                // 0..1
    const int wc = wid & 3;                 // 0..3
    const int b  = blockIdx.z;
    const int m0 = blockIdx.y * BM;
    const int n0 = blockIdx.x * 128;

    const __nv_bfloat16* pAh = Ah + (size_t)b * strA + (size_t)m0 * lda;
    const __nv_bfloat16* pAl = Al + (size_t)b * strA + (size_t)m0 * lda;
    const __nv_bfloat16* pBh = Bh + (size_t)b * strB + (size_t)n0 * ldb;
    const __nv_bfloat16* pBl = Bl + (size_t)b * strB + (size_t)n0 * ldb;

    float acc[TM][4][4] = {};
    float rs[TM][2];
    if (NORM) {
        #pragma unroll
        for (int t = 0; t < TM; t++) { rs[t][0] = 0.0f; rs[t][1] = 0.0f; }
    }

    const int a_rl = ((lane >> 3) & 1) * 8 + (lane & 7);
    const int a_cl = lane >> 4;
    const int b_rl = (lane >> 4) * 8 + (lane & 7);
    const int b_cl = (lane >> 3) & 1;

    auto load_stage = [&](int s, int kc) {
        const uint32_t st = sb + s * SS;
        const int k0 = kc * 32;
        #pragma unroll
        for (int i = tid; i < BM * 4; i += 256) {
            int r = i >> 2, c = i & 3;
            uint32_t so = st + r * 80 + c * 16;
            size_t g = (size_t)r * lda + k0 + c * 8;
            cpa16(so,           pAh + g);
            cpa16(so + A_BYTES, pAl + g);
        }
        #pragma unroll
        for (int i = tid; i < 512; i += 256) {
            int r = i >> 2, c = i & 3;
            uint32_t so = st + 2 * A_BYTES + r * 80 + c * 16;
            size_t g = (size_t)r * ldb + k0 + c * 8;
            cpa16(so,           pBh + g);
            cpa16(so + B_BYTES, pBl + g);
        }
    };

    load_stage(0, 0); cpa_commit();
    if (kchunks > 1) load_stage(1, 1);
    cpa_commit();

    for (int kc = 0; kc < kchunks; kc++) {
        cpa_wait1();
        __syncthreads();
        const uint32_t st = sb + (kc & 1) * SS;
        const uint32_t uAh = st, uAl = st + A_BYTES;
        const uint32_t uBh = st + 2 * A_BYTES, uBl = uBh + B_BYTES;

        #pragma unroll
        for (int ks = 0; ks < 2; ks++) {
            const int kk8 = ks * 2;
            uint32_t bh[4][2], bl[4][2];
            #pragma unroll
            for (int j2 = 0; j2 < 2; j2++) {
                int nrow = wc * 32 + j2 * 16 + b_rl;
                uint32_t off = (uint32_t)(nrow * 80 + (kk8 + b_cl) * 16);
                uint32_t r[4];
                ldsm_x4(r, uBh + off);
                bh[j2 * 2 + 0][0] = r[0]; bh[j2 * 2 + 0][1] = r[1];
                bh[j2 * 2 + 1][0] = r[2]; bh[j2 * 2 + 1][1] = r[3];
                ldsm_x4(r, uBl + off);
                bl[j2 * 2 + 0][0] = r[0]; bl[j2 * 2 + 0][1] = r[1];
                bl[j2 * 2 + 1][0] = r[2]; bl[j2 * 2 + 1][1] = r[3];
            }
            #pragma unroll
            for (int t = 0; t < TM; t++) {
                int mrow = wr * (BM / 2) + t * 16 + a_rl;
                uint32_t off = (uint32_t)(mrow * 80 + (kk8 + a_cl) * 16);
                uint32_t ah[4], al[4];
                ldsm_x4(ah, uAh + off);
                ldsm_x4(al, uAl + off);
                if (NORM && wc == 0) {
                    rs[t][0] += bf2sum(ah[0]) + bf2sum(ah[2]) + bf2sum(al[0]) + bf2sum(al[2]);
                    rs[t][1] += bf2sum(ah[1]) + bf2sum(ah[3]) + bf2sum(al[1]) + bf2sum(al[3]);
                }
                #pragma unroll
                for (int j = 0; j < 4; j++) mma_bf16(acc[t][j], ah, bh[j]);
                #pragma unroll
                for (int j = 0; j < 4; j++) mma_bf16(acc[t][j], ah, bl[j]);
                #pragma unroll
                for (int j = 0; j < 4; j++) mma_bf16(acc[t][j], al, bh[j]);
            }
        }
        __syncthreads();
        int nk = kc + 2;
        if (nk < kchunks) load_stage(kc & 1, nk);
        cpa_commit();
    }

    // ---- row-sum reduction (NORM) ----
    float* srow = (float*)(smem + 2 * SS);
    if (NORM) {
        #pragma unroll
        for (int t = 0; t < TM; t++)
            #pragma unroll
            for (int h = 0; h < 2; h++) {
                float v = rs[t][h];
                v += __shfl_xor_sync(0xffffffffu, v, 1);
                v += __shfl_xor_sync(0xffffffffu, v, 2);
                if (wc == 0 && (lane & 3) == 0)
                    srow[wr * (BM / 2) + t * 16 + (lane >> 2) + h * 8] = v;
            }
        __syncthreads();
    }

    // ---- epilogue ----
    #pragma unroll
    for (int t = 0; t < TM; t++) {
        int rloc = wr * (BM / 2) + t * 16 + (lane >> 2);
        int row = m0 + rloc;
        float inv0 = 1.0f, inv1 = 1.0f;
        if (NORM) { inv0 = 1.0f / srow[rloc]; inv1 = 1.0f / srow[rloc + 8]; }
        #pragma unroll
        for (int j = 0; j < 4; j++) {
            int col = n0 + wc * 32 + j * 8 + ((lane & 3) << 1);
            if (EPI == 1) {
                __nv_bfloat16* ph = Ch + (size_t)b * strC;
                __nv_bfloat16* pl = Cl + (size_t)b * strC;
                split_write2(ph + (size_t)row * ldc + col, pl + (size_t)row * ldc + col,
                             acc[t][j][0] * inv0, acc[t][j][1] * inv0);
                split_write2(ph + (size_t)(row + 8) * ldc + col, pl + (size_t)(row + 8) * ldc + col,
                             acc[t][j][2] * inv1, acc[t][j][3] * inv1);
            } else if (EPI == 3) {
                __nv_bfloat16* ph = Ch + (size_t)b * strC;
                __nv_bfloat16* pl = Cl + (size_t)b * strC;
                split_write2(ph + (size_t)row * ldc + col, pl + (size_t)row * ldc + col,
                             __expf(acc[t][j][0]), __expf(acc[t][j][1]));
                split_write2(ph + (size_t)(row + 8) * ldc + col, pl + (size_t)(row + 8) * ldc + col,
                             __expf(acc[t][j][2]), __expf(acc[t][j][3]));
            } else {
                float* Cp = C + (size_t)b * strC;
                float b0 = bias[row], b1 = bias[row + 8];
                *(float2*)(Cp + (size_t)row * ldc + col) =
                    make_float2(acc[t][j][0] + b0, acc[t][j][1] + b0);
                *(float2*)(Cp + (size_t)(row + 8) * ldc + col) =
                    make_float2(acc[t][j][2] + b1, acc[t][j][3] + b1);
            }
        }
    }
}

// ============================ projections (fp32 SIMT) ============================
// theta & phi in one launch (blockIdx.y selects), token-major outputs [n,d]
__global__ __launch_bounds__(256, 2)
void proj_qk(const float* __restrict__ x,
             const float* __restrict__ Wt, const float* __restrict__ bt,
             const float* __restrict__ Wp, const float* __restrict__ bp,
             __nv_bfloat16* __restrict__ th, __nv_bfloat16* __restrict__ tl,
             __nv_bfloat16* __restrict__ ph, __nv_bfloat16* __restrict__ pl)
{
    const float* W    = blockIdx.y ? Wp : Wt;
    const float* bias = blockIdx.y ? bp : bt;
    __nv_bfloat16* out_hi = blockIdx.y ? ph : th;
    __nv_bfloat16* out_lo = blockIdx.y ? pl : tl;

    __shared__ float As[8][132];
    __shared__ float Bs[8][132];
    const int b = blockIdx.z;
    const int m0 = blockIdx.x * 128;
    const float* A = x + (size_t)b * CHAN * NTOK;
    const int tid = threadIdx.x;
    const int tx = tid & 15, ty = tid >> 4;

    float acc[8][8] = {};
    for (int k0 = 0; k0 < CHAN; k0 += 8) {
        { int r = tid >> 5; int c = (tid & 31) << 2;
          float4 v = *(const float4*)(A + (size_t)(k0 + r) * NTOK + m0 + c);
          *(float4*)&As[r][c] = v; }
        { int r = tid >> 1; int q = (tid & 1) << 2;
          float4 v = *(const float4*)(W + (size_t)r * CHAN + k0 + q);
          Bs[q + 0][r] = v.x; Bs[q + 1][r] = v.y; Bs[q + 2][r] = v.z; Bs[q + 3][r] = v.w; }
        __syncthreads();
        #pragma unroll
        for (int k = 0; k < 8; k++) {
            float a[8], bb[8];
            *(float4*)&a[0] = *(float4*)&As[k][ty * 4];
            *(float4*)&a[4] = *(float4*)&As[k][ty * 4 + 64];
            *(float4*)&bb[0] = *(float4*)&Bs[k][tx * 4];
            *(float4*)&bb[4] = *(float4*)&Bs[k][tx * 4 + 64];
            #pragma unroll
            for (int i = 0; i < 8; i++)
                #pragma unroll
                for (int j = 0; j < 8; j++)
                    acc[i][j] = fmaf(a[i], bb[j], acc[i][j]);
        }
        __syncthreads();
    }
    float bv[8];
    #pragma unroll
    for (int jg = 0; jg < 2; jg++)
        #pragma unroll
        for (int j = 0; j < 4; j++) bv[jg * 4 + j] = bias[tx * 4 + jg * 64 + j];
    #pragma unroll
    for (int i = 0; i < 8; i++) {
        int m = m0 + ((i < 4) ? (ty * 4 + i) : (64 + ty * 4 + i - 4));
        __nv_bfloat16* oh = out_hi + ((size_t)b * NTOK + m) * DIM;
        __nv_bfloat16* ol = out_lo + ((size_t)b * NTOK + m) * DIM;
        #pragma unroll
        for (int jg = 0; jg < 2; jg++) {
            int n = tx * 4 + jg * 64;
            split_write4(oh + n, ol + n,
                         acc[i][jg * 4 + 0] + bv[jg * 4 + 0],
                         acc[i][jg * 4 + 1] + bv[jg * 4 + 1],
                         acc[i][jg * 4 + 2] + bv[jg * 4 + 2],
                         acc[i][jg * 4 + 3] + bv[jg * 4 + 3]);
        }
    }
}

// g projection, d-major output [d,m]
__global__ __launch_bounds__(256, 2)
void proj_dn(const float* __restrict__ x, const float* __restrict__ W,
             const float* __restrict__ bias,
             __nv_bfloat16* __restrict__ out_hi, __nv_bfloat16* __restrict__ out_lo)
{
    __shared__ float As[8][132];
    __shared__ float Bs[8][132];
    const int b = blockIdx.z;
    const int n0 = blockIdx.x * 128;
    const float* B = x + (size_t)b * CHAN * NTOK;
    const int tid = threadIdx.x;
    const int tx = tid & 15, ty = tid >> 4;

    float acc[8][8] = {};
    for (int k0 = 0; k0 < CHAN; k0 += 8) {
        { int r = tid >> 1; int q = (tid & 1) << 2;
          float4 v = *(const float4*)(W + (size_t)r * CHAN + k0 + q);
          As[q + 0][r] = v.x; As[q + 1][r] = v.y; As[q + 2][r] = v.z; As[q + 3][r] = v.w; }
        { int r = tid >> 5; int c = (tid & 31) << 2;
          float4 v = *(const float4*)(B + (size_t)(k0 + r) * NTOK + n0 + c);
          *(float4*)&Bs[r][c] = v; }
        __syncthreads();
        #pragma unroll
        for (int k = 0; k < 8; k++) {
            float a[8], bb[8];
            *(float4*)&a[0] = *(float4*)&As[k][ty * 4];
            *(float4*)&a[4] = *(float4*)&As[k][ty * 4 + 64];
            *(float4*)&bb[0] = *(float4*)&Bs[k][tx * 4];
            *(float4*)&bb[4] = *(float4*)&Bs[k][tx * 4 + 64];
            #pragma unroll
            for (int i = 0; i < 8; i++)
                #pragma unroll
                for (int j = 0; j < 8; j++)
                    acc[i][j] = fmaf(a[i], bb[j], acc[i][j]);
        }
        __syncthreads();
    }
    #pragma unroll
    for (int i = 0; i < 8; i++) {
        int m = (i < 4) ? (ty * 4 + i) : (64 + ty * 4 + i - 4);
        float bvm = bias[m];
        __nv_bfloat16* oh = out_hi + ((size_t)b * DIM + m) * NTOK;
        __nv_bfloat16* ol = out_lo + ((size_t)b * DIM + m) * NTOK;
        #pragma unroll
        for (int jg = 0; jg < 2; jg++) {
            int n = n0 + tx * 4 + jg * 64;
            split_write4(oh + n, ol + n,
                         acc[i][jg * 4 + 0] + bvm, acc[i][jg * 4 + 1] + bvm,
                         acc[i][jg * 4 + 2] + bvm, acc[i][jg * 4 + 3] + bvm);
        }
    }
}

// ============================ w_w split (tiny) ============================
__global__ __launch_bounds__(256)
void w_split(const float* __restrict__ w,
             __nv_bfloat16* __restrict__ hi, __nv_bfloat16* __restrict__ lo)
{
    int i = (blockIdx.x * 256 + threadIdx.x) * 4;
    float4 v = *(const float4*)(w + i);
    split_write4(hi + i, lo + i, v.x, v.y, v.z, v.w);
}

// ============================ batchnorm ============================
__global__ __launch_bounds__(256)
void bn_stats(const float* __restrict__ wy)
{
    const int c = blockIdx.x;
    const int t = threadIdx.x;
    float s1 = 0.0f, s2 = 0.0f;
    #pragma unroll
    for (int b = 0; b < BATCH; b++) {
        const float* p = wy + ((size_t)(b * CHAN + c) << 12);
        for (int i = t; i < NTOK; i += 256) {
            float x = p[i];
            s1 += x; s2 += x * x;
        }
    }
    #pragma unroll
    for (int o = 16; o; o >>= 1) {
        s1 += __shfl_xor_sync(0xffffffffu, s1, o);
        s2 += __shfl_xor_sync(0xffffffffu, s2, o);
    }
    __shared__ float r1[8], r2[8];
    if ((t & 31) == 0) { r1[t >> 5] = s1; r2[t >> 5] = s2; }
    __syncthreads();
    if (t == 0) {
        s1 = 0.0f; s2 = 0.0f;
        #pragma unroll
        for (int i = 0; i < 8; i++) { s1 += r1[i]; s2 += r2[i]; }
        float mean = s1 * (1.0f / 16384.0f);
        float var  = s2 * (1.0f / 16384.0f) - mean * mean;
        g_mean[c] = mean;
        g_istd[c] = rsqrtf(var + 1e-5f);
    }
}

__global__ __launch_bounds__(256)
void bn_apply(const float* __restrict__ wy, const float* __restrict__ x,
              const float* __restrict__ gamma, const float* __restrict__ beta,
              float* __restrict__ out)
{
    int i4 = blockIdx.x * 256 + threadIdx.x;
    int c = (i4 >> 10) & (CHAN - 1);
    float is = g_istd[c];
    float ga = gamma[c] * is;
    float be = beta[c] - g_mean[c] * ga;
    float4 w = ((const float4*)wy)[i4];
    float4 xx = ((const float4*)x)[i4];
    float4 o;
    o.x = w.x * ga + be + xx.x;
    o.y = w.y * ga + be + xx.y;
    o.z = w.z * ga + be + xx.z;
    o.w = w.w * ga + be + xx.w;
    ((float4*)out)[i4] = o;
}

// ============================ launch ============================
#define SMEM_128 (2 * (2 * 128 * 80 + 2 * 128 * 80))          // 81920
#define SMEM_PV  (2 * (2 * 64 * 80 + 2 * 128 * 80) + 256)     // 61696

extern "C" void kernel_launch(void* const* d_in, const int* in_sizes, int n_in,
                              void* d_out, int out_size)
{
    const float* x       = (const float*)d_in[0];
    const float* g_w     = (const float*)d_in[1];
    const float* g_b     = (const float*)d_in[2];
    const float* theta_w = (const float*)d_in[3];
    const float* theta_b = (const float*)d_in[4];
    const float* phi_w   = (const float*)d_in[5];
    const float* phi_b   = (const float*)d_in[6];
    const float* w_w     = (const float*)d_in[7];
    const float* w_b     = (const float*)d_in[8];
    const float* gamma   = (const float*)d_in[9];
    const float* beta    = (const float*)d_in[10];
    float* out = (float*)d_out;

    float* wy;
    __nv_bfloat16 *thh, *thl, *phh, *phl, *ghh, *ghl, *p_hi, *p_lo, *y_hi, *y_lo, *wwh, *wwl;
    cudaGetSymbolAddress((void**)&wy,   g_wy);
    cudaGetSymbolAddress((void**)&thh,  g_th_hi);
    cudaGetSymbolAddress((void**)&thl,  g_th_lo);
    cudaGetSymbolAddress((void**)&phh,  g_ph_hi);
    cudaGetSymbolAddress((void**)&phl,  g_ph_lo);
    cudaGetSymbolAddress((void**)&ghh,  g_g_hi);
    cudaGetSymbolAddress((void**)&ghl,  g_g_lo);
    cudaGetSymbolAddress((void**)&p_hi, g_p_hi);
    cudaGetSymbolAddress((void**)&p_lo, g_p_lo);
    cudaGetSymbolAddress((void**)&y_hi, g_y_hi);
    cudaGetSymbolAddress((void**)&y_lo, g_y_lo);
    cudaGetSymbolAddress((void**)&wwh,  g_ww_hi);
    cudaGetSymbolAddress((void**)&wwl,  g_ww_lo);

    cudaFuncSetAttribute((void*)mma_tt<128, 3, false>, cudaFuncAttributeMaxDynamicSharedMemorySize, SMEM_128);
    cudaFuncSetAttribute((void*)mma_tt<64, 1, true>,   cudaFuncAttributeMaxDynamicSharedMemorySize, SMEM_PV);
    cudaFuncSetAttribute((void*)mma_tt<128, 2, false>, cudaFuncAttributeMaxDynamicSharedMemorySize, SMEM_128);

    // projections + weight split
    proj_qk<<<dim3(32, 2, BATCH), 256>>>(x, theta_w, theta_b, phi_w, phi_b,
                                         thh, thl, phh, phl);
    proj_dn<<<dim3(32, 1, BATCH), 256>>>(x, g_w, g_b, ghh, ghl);
    w_split<<<CHAN * DIM / 1024, 256>>>(w_w, wwh, wwl);

    // P_unnorm[n,m] = exp(theta[n,:] . phi[m,:])  (no max subtraction needed)
    mma_tt<128, 3, false><<<dim3(32, 32, BATCH), 256, SMEM_128>>>(
        thh, thl, phh, phl, nullptr, p_hi, p_lo, nullptr,
        DIM, DIM, NTOK, DIM / 32,
        (size_t)NTOK * DIM, (size_t)NTOK * DIM, (size_t)NTOK * NTOK);

    // y[n,d] = (P_unnorm[n,:] . g[d,:]) / rowsum  -> bf16 hi/lo
    mma_tt<64, 1, true><<<dim3(1, 64, BATCH), 256, SMEM_PV>>>(
        p_hi, p_lo, ghh, ghl, nullptr, y_hi, y_lo, nullptr,
        NTOK, NTOK, DIM, NTOK / 32,
        (size_t)NTOK * NTOK, (size_t)DIM * NTOK, (size_t)NTOK * DIM);

    // wy[c,n] = w_w[c,:] . y[n,:] + w_b[c]
    mma_tt<128, 2, false><<<dim3(32, 2, BATCH), 256, SMEM_128>>>(
        wwh, wwl, y_hi, y_lo, wy, nullptr, nullptr, w_b,
        DIM, DIM, NTOK, DIM / 32,
        0, (size_t)NTOK * DIM, (size_t)CHAN * NTOK);

    // batchnorm + residual
    bn_stats<<<CHAN, 256>>>(wy);
    bn_apply<<<(BATCH * CHAN * NTOK / 4) / 256, 256>>>(wy, x, gamma, beta, out);
}

// round 6
// speedup vs baseline: 3.0208x; 1.3100x over previous
#include <cuda_runtime.h>
#include <cuda_bf16.h>
#include <cstdint>
#include <math.h>

#define BATCH 4
#define CHAN  256
#define DIM   128
#define NTOK  4096

// ============================ scratch ============================
__device__ __nv_bfloat16 g_th_hi[BATCH * NTOK * DIM];  // theta token-major [n,d]
__device__ __nv_bfloat16 g_th_lo[BATCH * NTOK * DIM];
__device__ __nv_bfloat16 g_ph_hi[BATCH * NTOK * DIM];  // phi token-major [m,d]
__device__ __nv_bfloat16 g_ph_lo[BATCH * NTOK * DIM];
__device__ __nv_bfloat16 g_g_hi[BATCH * DIM * NTOK];   // g d-major [d,m]
__device__ __nv_bfloat16 g_g_lo[BATCH * DIM * NTOK];
__device__ __nv_bfloat16 g_y_hi[BATCH * NTOK * DIM];   // y token-major [n,d] (normalized)
__device__ __nv_bfloat16 g_y_lo[BATCH * NTOK * DIM];
__device__ __nv_bfloat16 g_ww_hi[CHAN * DIM];
__device__ __nv_bfloat16 g_ww_lo[CHAN * DIM];
__device__ float g_wy[BATCH * CHAN * NTOK];
__device__ float g_mean[CHAN];
__device__ float g_istd[CHAN];

// ============================ helpers ============================
__device__ __forceinline__ uint32_t smem_to_u32(const void* p) {
    uint32_t a;
    asm("{ .reg .u64 t; cvta.to.shared.u64 t, %1; cvt.u32.u64 %0, t; }" : "=r"(a) : "l"(p));
    return a;
}
__device__ __forceinline__ void cpa16(uint32_t saddr, const void* g) {
    asm volatile("cp.async.cg.shared.global [%0], [%1], 16;" :: "r"(saddr), "l"(g));
}
__device__ __forceinline__ void cpa_commit() {
    asm volatile("cp.async.commit_group;" ::: "memory");
}
__device__ __forceinline__ void cpa_wait1() {
    asm volatile("cp.async.wait_group 1;" ::: "memory");
}
__device__ __forceinline__ void ldsm_x4(uint32_t* r, uint32_t addr) {
    asm volatile("ldmatrix.sync.aligned.m8n8.x4.shared.b16 {%0,%1,%2,%3}, [%4];"
                 : "=r"(r[0]), "=r"(r[1]), "=r"(r[2]), "=r"(r[3]) : "r"(addr));
}
__device__ __forceinline__ void mma_bf16(float* c, const uint32_t* a, const uint32_t* b) {
    asm volatile("mma.sync.aligned.m16n8k16.row.col.f32.bf16.bf16.f32 "
                 "{%0,%1,%2,%3}, {%4,%5,%6,%7}, {%8,%9}, {%0,%1,%2,%3};"
                 : "+f"(c[0]), "+f"(c[1]), "+f"(c[2]), "+f"(c[3])
                 : "r"(a[0]), "r"(a[1]), "r"(a[2]), "r"(a[3]), "r"(b[0]), "r"(b[1]));
}
__device__ __forceinline__ void split_write4(__nv_bfloat16* hi, __nv_bfloat16* lo,
                                             float a, float b, float c, float d) {
    __nv_bfloat16 h0 = __float2bfloat16_rn(a), h1 = __float2bfloat16_rn(b);
    __nv_bfloat16 h2 = __float2bfloat16_rn(c), h3 = __float2bfloat16_rn(d);
    __nv_bfloat16 l0 = __float2bfloat16_rn(a - __bfloat162float(h0));
    __nv_bfloat16 l1 = __float2bfloat16_rn(b - __bfloat162float(h1));
    __nv_bfloat16 l2 = __float2bfloat16_rn(c - __bfloat162float(h2));
    __nv_bfloat16 l3 = __float2bfloat16_rn(d - __bfloat162float(h3));
    *(__nv_bfloat162*)(hi + 0) = __nv_bfloat162(h0, h1);
    *(__nv_bfloat162*)(hi + 2) = __nv_bfloat162(h2, h3);
    *(__nv_bfloat162*)(lo + 0) = __nv_bfloat162(l0, l1);
    *(__nv_bfloat162*)(lo + 2) = __nv_bfloat162(l2, l3);
}
__device__ __forceinline__ void split_write2(__nv_bfloat16* hi, __nv_bfloat16* lo,
                                             float a, float b) {
    __nv_bfloat16 h0 = __float2bfloat16_rn(a), h1 = __float2bfloat16_rn(b);
    __nv_bfloat16 l0 = __float2bfloat16_rn(a - __bfloat162float(h0));
    __nv_bfloat16 l1 = __float2bfloat16_rn(b - __bfloat162float(h1));
    *(__nv_bfloat162*)hi = __nv_bfloat162(h0, h1);
    *(__nv_bfloat162*)lo = __nv_bfloat162(l0, l1);
}
// pack two floats as bf16x2 hi frag, emit lo frag
__device__ __forceinline__ uint32_t pack_split(float a, float b, uint32_t& lo_out) {
    __nv_bfloat16 ha = __float2bfloat16_rn(a), hb = __float2bfloat16_rn(b);
    __nv_bfloat16 la = __float2bfloat16_rn(a - __bfloat162float(ha));
    __nv_bfloat16 lb = __float2bfloat16_rn(b - __bfloat162float(hb));
    __nv_bfloat162 h(ha, hb), l(la, lb);
    lo_out = *(uint32_t*)&l;
    return *(uint32_t*)&h;
}

// ============================ fused attention kernel ============================
// Per CTA: 128 query rows (m-tile), loop over 64-key blocks.
//   S = theta . phi^T  (K=128, 3-pass split bf16)  -> exp in-register ->
//   P frags (hi/lo) reused directly as A operands -> y += P . g (3-pass)
//   y normalized by row sums of quantized P, written as bf16 hi/lo.
#define TH_STR   272
#define PHI_STR  272
#define G_STR    144
#define TH_HALF  (128 * TH_STR)       // 34816
#define TH_BYTES (2 * TH_HALF)        // 69632
#define PHI_HALF (64 * PHI_STR)       // 17408
#define PHI_STAGE (2 * PHI_HALF)      // 34816
#define G_HALF   (128 * G_STR)        // 18432
#define G_STAGE  (2 * G_HALF)         // 36864
#define PHI_OFF  TH_BYTES
#define G_OFF    (PHI_OFF + 2 * PHI_STAGE)
#define FUSED_SMEM (G_OFF + 2 * G_STAGE)   // 212992 bytes

__global__ __launch_bounds__(256, 1)
void fused_attn(const __nv_bfloat16* __restrict__ thh, const __nv_bfloat16* __restrict__ thl,
                const __nv_bfloat16* __restrict__ phh, const __nv_bfloat16* __restrict__ phl,
                const __nv_bfloat16* __restrict__ ghh, const __nv_bfloat16* __restrict__ ghl,
                __nv_bfloat16* __restrict__ y_hi, __nv_bfloat16* __restrict__ y_lo)
{
    extern __shared__ char smem[];
    const uint32_t sb = smem_to_u32(smem);
    const int tid = threadIdx.x;
    const int lane = tid & 31, wid = tid >> 5;
    const int b = blockIdx.y;
    const int m0 = blockIdx.x * 128;

    const __nv_bfloat16* pth = thh + ((size_t)b * NTOK + m0) * DIM;
    const __nv_bfloat16* ptl = thl + ((size_t)b * NTOK + m0) * DIM;
    const __nv_bfloat16* pph = phh + (size_t)b * NTOK * DIM;
    const __nv_bfloat16* ppl = phl + (size_t)b * NTOK * DIM;
    const __nv_bfloat16* pgh = ghh + (size_t)b * DIM * NTOK;
    const __nv_bfloat16* pgl = ghl + (size_t)b * DIM * NTOK;

    // ---- load theta tile (128 x 128, hi/lo) ----
    #pragma unroll
    for (int i = tid; i < 4096; i += 256) {
        int h = i >> 11, rem = i & 2047;
        int r = rem >> 4, c = rem & 15;
        const __nv_bfloat16* src = h ? ptl : pth;
        cpa16(sb + h * TH_HALF + r * TH_STR + c * 16, src + (size_t)r * DIM + c * 8);
    }

    auto load_stage = [&](int s, int nt) {
        // phi block: 64 token rows x 128 d
        uint32_t pb = sb + PHI_OFF + s * PHI_STAGE;
        const __nv_bfloat16* sph = pph + (size_t)(nt * 64) * DIM;
        const __nv_bfloat16* spl = ppl + (size_t)(nt * 64) * DIM;
        #pragma unroll
        for (int i = tid; i < 2048; i += 256) {
            int h = i >> 10, rem = i & 1023;
            int r = rem >> 4, c = rem & 15;
            const __nv_bfloat16* src = h ? spl : sph;
            cpa16(pb + h * PHI_HALF + r * PHI_STR + c * 16, src + (size_t)r * DIM + c * 8);
        }
        // g block: 128 d rows x 64 tokens
        uint32_t gb = sb + G_OFF + s * G_STAGE;
        const __nv_bfloat16* sgh = pgh + nt * 64;
        const __nv_bfloat16* sgl = pgl + nt * 64;
        #pragma unroll
        for (int i = tid; i < 2048; i += 256) {
            int h = i >> 10, rem = i & 1023;
            int r = rem >> 3, c = rem & 7;
            const __nv_bfloat16* src = h ? sgl : sgh;
            cpa16(gb + h * G_HALF + r * G_STR + c * 16, src + (size_t)r * NTOK + c * 8);
        }
    };

    load_stage(0, 0); cpa_commit();       // group: theta + stage0
    load_stage(1, 1); cpa_commit();       // group: stage1

    float yacc[16][4] = {};
    float rs0 = 0.0f, rs1 = 0.0f;

    const int a_rl = ((lane >> 3) & 1) * 8 + (lane & 7);
    const int a_cl = lane >> 4;
    const int b_rl = (lane >> 4) * 8 + (lane & 7);
    const int b_cl = (lane >> 3) & 1;
    const uint32_t a_base = sb + (uint32_t)(16 * wid + a_rl) * TH_STR + a_cl * 16;

    for (int nt = 0; nt < 64; nt++) {
        cpa_wait1();
        __syncthreads();
        const uint32_t uph = sb + PHI_OFF + (nt & 1) * PHI_STAGE;
        const uint32_t ug  = sb + G_OFF + (nt & 1) * G_STAGE;

        // ---- S = theta . phi^T over K=128 (8 ksteps), 3-pass ----
        float S[8][4] = {};
        #pragma unroll
        for (int ks = 0; ks < 8; ks++) {
            uint32_t ath[4], atl[4];
            uint32_t aoff = a_base + ks * 32;
            ldsm_x4(ath, aoff);
            ldsm_x4(atl, aoff + TH_HALF);
            uint32_t bh[8][2], bl[8][2];
            #pragma unroll
            for (int f = 0; f < 4; f++) {
                uint32_t boff = (uint32_t)(16 * f + b_rl) * PHI_STR + (2 * ks + b_cl) * 16;
                uint32_t r[4];
                ldsm_x4(r, uph + boff);
                bh[2 * f][0] = r[0]; bh[2 * f][1] = r[1];
                bh[2 * f + 1][0] = r[2]; bh[2 * f + 1][1] = r[3];
                ldsm_x4(r, uph + PHI_HALF + boff);
                bl[2 * f][0] = r[0]; bl[2 * f][1] = r[1];
                bl[2 * f + 1][0] = r[2]; bl[2 * f + 1][1] = r[3];
            }
            #pragma unroll
            for (int j = 0; j < 8; j++) mma_bf16(S[j], ath, bh[j]);
            #pragma unroll
            for (int j = 0; j < 8; j++) mma_bf16(S[j], ath, bl[j]);
            #pragma unroll
            for (int j = 0; j < 8; j++) mma_bf16(S[j], atl, bh[j]);
        }

        // ---- exp + split + rowsum; repack C-frags as A-frags ----
        uint32_t Ph[4][4], Pl[4][4];
        #pragma unroll
        for (int kk = 0; kk < 4; kk++) {
            float e0 = __expf(S[2 * kk][0]),     e1 = __expf(S[2 * kk][1]);
            float e2 = __expf(S[2 * kk][2]),     e3 = __expf(S[2 * kk][3]);
            float e4 = __expf(S[2 * kk + 1][0]), e5 = __expf(S[2 * kk + 1][1]);
            float e6 = __expf(S[2 * kk + 1][2]), e7 = __expf(S[2 * kk + 1][3]);
            rs0 += (e0 + e1) + (e4 + e5);
            rs1 += (e2 + e3) + (e6 + e7);
            Ph[kk][0] = pack_split(e0, e1, Pl[kk][0]);
            Ph[kk][1] = pack_split(e2, e3, Pl[kk][1]);
            Ph[kk][2] = pack_split(e4, e5, Pl[kk][2]);
            Ph[kk][3] = pack_split(e6, e7, Pl[kk][3]);
        }

        // ---- y += P . g over this 64-key block (4 ksteps), 3-pass ----
        #pragma unroll
        for (int ks2 = 0; ks2 < 4; ks2++) {
            uint32_t gh[16][2], gl[16][2];
            #pragma unroll
            for (int dd = 0; dd < 8; dd++) {
                uint32_t boff = (uint32_t)(16 * dd + b_rl) * G_STR + (2 * ks2 + b_cl) * 16;
                uint32_t r[4];
                ldsm_x4(r, ug + boff);
                gh[2 * dd][0] = r[0]; gh[2 * dd][1] = r[1];
                gh[2 * dd + 1][0] = r[2]; gh[2 * dd + 1][1] = r[3];
                ldsm_x4(r, ug + G_HALF + boff);
                gl[2 * dd][0] = r[0]; gl[2 * dd][1] = r[1];
                gl[2 * dd + 1][0] = r[2]; gl[2 * dd + 1][1] = r[3];
            }
            #pragma unroll
            for (int j = 0; j < 16; j++) mma_bf16(yacc[j], Ph[ks2], gh[j]);
            #pragma unroll
            for (int j = 0; j < 16; j++) mma_bf16(yacc[j], Ph[ks2], gl[j]);
            #pragma unroll
            for (int j = 0; j < 16; j++) mma_bf16(yacc[j], Pl[ks2], gh[j]);
        }

        __syncthreads();
        if (nt + 2 < 64) load_stage(nt & 1, nt + 2);
        cpa_commit();
    }

    // ---- normalize + write ----
    rs0 += __shfl_xor_sync(0xffffffffu, rs0, 1);
    rs0 += __shfl_xor_sync(0xffffffffu, rs0, 2);
    rs1 += __shfl_xor_sync(0xffffffffu, rs1, 1);
    rs1 += __shfl_xor_sync(0xffffffffu, rs1, 2);
    float inv0 = 1.0f / rs0, inv1 = 1.0f / rs1;

    int row = m0 + 16 * wid + (lane >> 2);
    __nv_bfloat16* yh = y_hi + (size_t)b * NTOK * DIM;
    __nv_bfloat16* yl = y_lo + (size_t)b * NTOK * DIM;
    #pragma unroll
    for (int j = 0; j < 16; j++) {
        int col = 8 * j + 2 * (lane & 3);
        split_write2(yh + (size_t)row * DIM + col, yl + (size_t)row * DIM + col,
                     yacc[j][0] * inv0, yacc[j][1] * inv0);
        split_write2(yh + (size_t)(row + 8) * DIM + col, yl + (size_t)(row + 8) * DIM + col,
                     yacc[j][2] * inv1, yacc[j][3] * inv1);
    }
}

// ============================ pipelined mma.sync GEMM (wy) ============================
// C[m,n] = sum_k A[m,k]*B[n,k] + bias[m], split bf16 3-pass, 2-stage cp.async.
__global__ __launch_bounds__(256, 2)
void mma_wy(const __nv_bfloat16* __restrict__ Ah, const __nv_bfloat16* __restrict__ Al,
            const __nv_bfloat16* __restrict__ Bh, const __nv_bfloat16* __restrict__ Bl,
            float* __restrict__ C, const float* __restrict__ bias,
            int lda, int ldb, int ldc, int kchunks,
            size_t strB, size_t strC)
{
    constexpr int A_BYTES = 128 * 80;
    constexpr int B_BYTES = 128 * 80;
    constexpr int SS = 2 * A_BYTES + 2 * B_BYTES;

    extern __shared__ char smem[];
    const uint32_t sb = smem_to_u32(smem);

    const int tid = threadIdx.x;
    const int lane = tid & 31, wid = tid >> 5;
    const int wr = wid >> 2;
    const int wc = wid & 3;
    const int b  = blockIdx.z;
    const int m0 = blockIdx.y * 128;
    const int n0 = blockIdx.x * 128;

    const __nv_bfloat16* pAh = Ah + (size_t)m0 * lda;
    const __nv_bfloat16* pAl = Al + (size_t)m0 * lda;
    const __nv_bfloat16* pBh = Bh + (size_t)b * strB + (size_t)n0 * ldb;
    const __nv_bfloat16* pBl = Bl + (size_t)b * strB + (size_t)n0 * ldb;

    float acc[4][4][4] = {};

    const int a_rl = ((lane >> 3) & 1) * 8 + (lane & 7);
    const int a_cl = lane >> 4;
    const int b_rl = (lane >> 4) * 8 + (lane & 7);
    const int b_cl = (lane >> 3) & 1;

    auto load_stage = [&](int s, int kc) {
        const uint32_t st = sb + s * SS;
        const int k0 = kc * 32;
        #pragma unroll
        for (int i = tid; i < 512; i += 256) {
            int r = i >> 2, c = i & 3;
            uint32_t so = st + r * 80 + c * 16;
            size_t g = (size_t)r * lda + k0 + c * 8;
            cpa16(so,           pAh + g);
            cpa16(so + A_BYTES, pAl + g);
        }
        #pragma unroll
        for (int i = tid; i < 512; i += 256) {
            int r = i >> 2, c = i & 3;
            uint32_t so = st + 2 * A_BYTES + r * 80 + c * 16;
            size_t g = (size_t)r * ldb + k0 + c * 8;
            cpa16(so,           pBh + g);
            cpa16(so + B_BYTES, pBl + g);
        }
    };

    load_stage(0, 0); cpa_commit();
    if (kchunks > 1) load_stage(1, 1);
    cpa_commit();

    for (int kc = 0; kc < kchunks; kc++) {
        cpa_wait1();
        __syncthreads();
        const uint32_t st = sb + (kc & 1) * SS;
        const uint32_t uAh = st, uAl = st + A_BYTES;
        const uint32_t uBh = st + 2 * A_BYTES, uBl = uBh + B_BYTES;

        #pragma unroll
        for (int ks = 0; ks < 2; ks++) {
            const int kk8 = ks * 2;
            uint32_t bh[4][2], bl[4][2];
            #pragma unroll
            for (int j2 = 0; j2 < 2; j2++) {
                int nrow = wc * 32 + j2 * 16 + b_rl;
                uint32_t off = (uint32_t)(nrow * 80 + (kk8 + b_cl) * 16);
                uint32_t r[4];
                ldsm_x4(r, uBh + off);
                bh[j2 * 2 + 0][0] = r[0]; bh[j2 * 2 + 0][1] = r[1];
                bh[j2 * 2 + 1][0] = r[2]; bh[j2 * 2 + 1][1] = r[3];
                ldsm_x4(r, uBl + off);
                bl[j2 * 2 + 0][0] = r[0]; bl[j2 * 2 + 0][1] = r[1];
                bl[j2 * 2 + 1][0] = r[2]; bl[j2 * 2 + 1][1] = r[3];
            }
            #pragma unroll
            for (int t = 0; t < 4; t++) {
                int mrow = wr * 64 + t * 16 + a_rl;
                uint32_t off = (uint32_t)(mrow * 80 + (kk8 + a_cl) * 16);
                uint32_t ah[4], al[4];
                ldsm_x4(ah, uAh + off);
                ldsm_x4(al, uAl + off);
                #pragma unroll
                for (int j = 0; j < 4; j++) mma_bf16(acc[t][j], ah, bh[j]);
                #pragma unroll
                for (int j = 0; j < 4; j++) mma_bf16(acc[t][j], ah, bl[j]);
                #pragma unroll
                for (int j = 0; j < 4; j++) mma_bf16(acc[t][j], al, bh[j]);
            }
        }
        __syncthreads();
        int nk = kc + 2;
        if (nk < kchunks) load_stage(kc & 1, nk);
        cpa_commit();
    }

    float* Cp = C + (size_t)b * strC;
    #pragma unroll
    for (int t = 0; t < 4; t++) {
        int row = m0 + wr * 64 + t * 16 + (lane >> 2);
        float b0 = bias[row], b1 = bias[row + 8];
        #pragma unroll
        for (int j = 0; j < 4; j++) {
            int col = n0 + wc * 32 + j * 8 + ((lane & 3) << 1);
            *(float2*)(Cp + (size_t)row * ldc + col) =
                make_float2(acc[t][j][0] + b0, acc[t][j][1] + b0);
            *(float2*)(Cp + (size_t)(row + 8) * ldc + col) =
                make_float2(acc[t][j][2] + b1, acc[t][j][3] + b1);
        }
    }
}

// ============================ projections (fp32 SIMT) ============================
__global__ __launch_bounds__(256, 2)
void proj_qk(const float* __restrict__ x,
             const float* __restrict__ Wt, const float* __restrict__ bt,
             const float* __restrict__ Wp, const float* __restrict__ bp,
             __nv_bfloat16* __restrict__ th, __nv_bfloat16* __restrict__ tl,
             __nv_bfloat16* __restrict__ ph, __nv_bfloat16* __restrict__ pl)
{
    const float* W    = blockIdx.y ? Wp : Wt;
    const float* bias = blockIdx.y ? bp : bt;
    __nv_bfloat16* out_hi = blockIdx.y ? ph : th;
    __nv_bfloat16* out_lo = blockIdx.y ? pl : tl;

    __shared__ float As[8][132];
    __shared__ float Bs[8][132];
    const int b = blockIdx.z;
    const int m0 = blockIdx.x * 128;
    const float* A = x + (size_t)b * CHAN * NTOK;
    const int tid = threadIdx.x;
    const int tx = tid & 15, ty = tid >> 4;

    float acc[8][8] = {};
    for (int k0 = 0; k0 < CHAN; k0 += 8) {
        { int r = tid >> 5; int c = (tid & 31) << 2;
          float4 v = *(const float4*)(A + (size_t)(k0 + r) * NTOK + m0 + c);
          *(float4*)&As[r][c] = v; }
        { int r = tid >> 1; int q = (tid & 1) << 2;
          float4 v = *(const float4*)(W + (size_t)r * CHAN + k0 + q);
          Bs[q + 0][r] = v.x; Bs[q + 1][r] = v.y; Bs[q + 2][r] = v.z; Bs[q + 3][r] = v.w; }
        __syncthreads();
        #pragma unroll
        for (int k = 0; k < 8; k++) {
            float a[8], bb[8];
            *(float4*)&a[0] = *(float4*)&As[k][ty * 4];
            *(float4*)&a[4] = *(float4*)&As[k][ty * 4 + 64];
            *(float4*)&bb[0] = *(float4*)&Bs[k][tx * 4];
            *(float4*)&bb[4] = *(float4*)&Bs[k][tx * 4 + 64];
            #pragma unroll
            for (int i = 0; i < 8; i++)
                #pragma unroll
                for (int j = 0; j < 8; j++)
                    acc[i][j] = fmaf(a[i], bb[j], acc[i][j]);
        }
        __syncthreads();
    }
    float bv[8];
    #pragma unroll
    for (int jg = 0; jg < 2; jg++)
        #pragma unroll
        for (int j = 0; j < 4; j++) bv[jg * 4 + j] = bias[tx * 4 + jg * 64 + j];
    #pragma unroll
    for (int i = 0; i < 8; i++) {
        int m = m0 + ((i < 4) ? (ty * 4 + i) : (64 + ty * 4 + i - 4));
        __nv_bfloat16* oh = out_hi + ((size_t)b * NTOK + m) * DIM;
        __nv_bfloat16* ol = out_lo + ((size_t)b * NTOK + m) * DIM;
        #pragma unroll
        for (int jg = 0; jg < 2; jg++) {
            int n = tx * 4 + jg * 64;
            split_write4(oh + n, ol + n,
                         acc[i][jg * 4 + 0] + bv[jg * 4 + 0],
                         acc[i][jg * 4 + 1] + bv[jg * 4 + 1],
                         acc[i][jg * 4 + 2] + bv[jg * 4 + 2],
                         acc[i][jg * 4 + 3] + bv[jg * 4 + 3]);
        }
    }
}

__global__ __launch_bounds__(256, 2)
void proj_dn(const float* __restrict__ x, const float* __restrict__ W,
             const float* __restrict__ bias,
             __nv_bfloat16* __restrict__ out_hi, __nv_bfloat16* __restrict__ out_lo)
{
    __shared__ float As[8][132];
    __shared__ float Bs[8][132];
    const int b = blockIdx.z;
    const int n0 = blockIdx.x * 128;
    const float* B = x + (size_t)b * CHAN * NTOK;
    const int tid = threadIdx.x;
    const int tx = tid & 15, ty = tid >> 4;

    float acc[8][8] = {};
    for (int k0 = 0; k0 < CHAN; k0 += 8) {
        { int r = tid >> 1; int q = (tid & 1) << 2;
          float4 v = *(const float4*)(W + (size_t)r * CHAN + k0 + q);
          As[q + 0][r] = v.x; As[q + 1][r] = v.y; As[q + 2][r] = v.z; As[q + 3][r] = v.w; }
        { int r = tid >> 5; int c = (tid & 31) << 2;
          float4 v = *(const float4*)(B + (size_t)(k0 + r) * NTOK + n0 + c);
          *(float4*)&Bs[r][c] = v; }
        __syncthreads();
        #pragma unroll
        for (int k = 0; k < 8; k++) {
            float a[8], bb[8];
            *(float4*)&a[0] = *(float4*)&As[k][ty * 4];
            *(float4*)&a[4] = *(float4*)&As[k][ty * 4 + 64];
            *(float4*)&bb[0] = *(float4*)&Bs[k][tx * 4];
            *(float4*)&bb[4] = *(float4*)&Bs[k][tx * 4 + 64];
            #pragma unroll
            for (int i = 0; i < 8; i++)
                #pragma unroll
                for (int j = 0; j < 8; j++)
                    acc[i][j] = fmaf(a[i], bb[j], acc[i][j]);
        }
        __syncthreads();
    }
    #pragma unroll
    for (int i = 0; i < 8; i++) {
        int m = (i < 4) ? (ty * 4 + i) : (64 + ty * 4 + i - 4);
        float bvm = bias[m];
        __nv_bfloat16* oh = out_hi + ((size_t)b * DIM + m) * NTOK;
        __nv_bfloat16* ol = out_lo + ((size_t)b * DIM + m) * NTOK;
        #pragma unroll
        for (int jg = 0; jg < 2; jg++) {
            int n = n0 + tx * 4 + jg * 64;
            split_write4(oh + n, ol + n,
                         acc[i][jg * 4 + 0] + bvm, acc[i][jg * 4 + 1] + bvm,
                         acc[i][jg * 4 + 2] + bvm, acc[i][jg * 4 + 3] + bvm);
        }
    }
}

// ============================ w_w split (tiny) ============================
__global__ __launch_bounds__(256)
void w_split(const float* __restrict__ w,
             __nv_bfloat16* __restrict__ hi, __nv_bfloat16* __restrict__ lo)
{
    int i = (blockIdx.x * 256 + threadIdx.x) * 4;
    float4 v = *(const float4*)(w + i);
    split_write4(hi + i, lo + i, v.x, v.y, v.z, v.w);
}

// ============================ batchnorm ============================
__global__ __launch_bounds__(256)
void bn_stats(const float* __restrict__ wy)
{
    const int c = blockIdx.x;
    const int t = threadIdx.x;
    float s1 = 0.0f, s2 = 0.0f;
    #pragma unroll
    for (int b = 0; b < BATCH; b++) {
        const float* p = wy + ((size_t)(b * CHAN + c) << 12);
        for (int i = t; i < NTOK; i += 256) {
            float x = p[i];
            s1 += x; s2 += x * x;
        }
    }
    #pragma unroll
    for (int o = 16; o; o >>= 1) {
        s1 += __shfl_xor_sync(0xffffffffu, s1, o);
        s2 += __shfl_xor_sync(0xffffffffu, s2, o);
    }
    __shared__ float r1[8], r2[8];
    if ((t & 31) == 0) { r1[t >> 5] = s1; r2[t >> 5] = s2; }
    __syncthreads();
    if (t == 0) {
        s1 = 0.0f; s2 = 0.0f;
        #pragma unroll
        for (int i = 0; i < 8; i++) { s1 += r1[i]; s2 += r2[i]; }
        float mean = s1 * (1.0f / 16384.0f);
        float var  = s2 * (1.0f / 16384.0f) - mean * mean;
        g_mean[c] = mean;
        g_istd[c] = rsqrtf(var + 1e-5f);
    }
}

__global__ __launch_bounds__(256)
void bn_apply(const float* __restrict__ wy, const float* __restrict__ x,
              const float* __restrict__ gamma, const float* __restrict__ beta,
              float* __restrict__ out)
{
    int i4 = blockIdx.x * 256 + threadIdx.x;
    int c = (i4 >> 10) & (CHAN - 1);
    float is = g_istd[c];
    float ga = gamma[c] * is;
    float be = beta[c] - g_mean[c] * ga;
    float4 w = ((const float4*)wy)[i4];
    float4 xx = ((const float4*)x)[i4];
    float4 o;
    o.x = w.x * ga + be + xx.x;
    o.y = w.y * ga + be + xx.y;
    o.z = w.z * ga + be + xx.z;
    o.w = w.w * ga + be + xx.w;
    ((float4*)out)[i4] = o;
}

// ============================ launch ============================
#define SMEM_WY (2 * (2 * 128 * 80 + 2 * 128 * 80))   // 81920

extern "C" void kernel_launch(void* const* d_in, const int* in_sizes, int n_in,
                              void* d_out, int out_size)
{
    const float* x       = (const float*)d_in[0];
    const float* g_w     = (const float*)d_in[1];
    const float* g_b     = (const float*)d_in[2];
    const float* theta_w = (const float*)d_in[3];
    const float* theta_b = (const float*)d_in[4];
    const float* phi_w   = (const float*)d_in[5];
    const float* phi_b   = (const float*)d_in[6];
    const float* w_w     = (const float*)d_in[7];
    const float* w_b     = (const float*)d_in[8];
    const float* gamma   = (const float*)d_in[9];
    const float* beta    = (const float*)d_in[10];
    float* out = (float*)d_out;

    float* wy;
    __nv_bfloat16 *thh, *thl, *phh, *phl, *ghh, *ghl, *y_hi, *y_lo, *wwh, *wwl;
    cudaGetSymbolAddress((void**)&wy,   g_wy);
    cudaGetSymbolAddress((void**)&thh,  g_th_hi);
    cudaGetSymbolAddress((void**)&thl,  g_th_lo);
    cudaGetSymbolAddress((void**)&phh,  g_ph_hi);
    cudaGetSymbolAddress((void**)&phl,  g_ph_lo);
    cudaGetSymbolAddress((void**)&ghh,  g_g_hi);
    cudaGetSymbolAddress((void**)&ghl,  g_g_lo);
    cudaGetSymbolAddress((void**)&y_hi, g_y_hi);
    cudaGetSymbolAddress((void**)&y_lo, g_y_lo);
    cudaGetSymbolAddress((void**)&wwh,  g_ww_hi);
    cudaGetSymbolAddress((void**)&wwl,  g_ww_lo);

    cudaFuncSetAttribute(fused_attn, cudaFuncAttributeMaxDynamicSharedMemorySize, FUSED_SMEM);
    cudaFuncSetAttribute(mma_wy, cudaFuncAttributeMaxDynamicSharedMemorySize, SMEM_WY);

    // projections + weight split
    proj_qk<<<dim3(32, 2, BATCH), 256>>>(x, theta_w, theta_b, phi_w, phi_b,
                                         thh, thl, phh, phl);
    proj_dn<<<dim3(32, 1, BATCH), 256>>>(x, g_w, g_b, ghh, ghl);
    w_split<<<CHAN * DIM / 1024, 256>>>(w_w, wwh, wwl);

    // fused: S = theta.phi^T -> exp -> y = (P.g)/rowsum  -> bf16 hi/lo
    fused_attn<<<dim3(32, BATCH), 256, FUSED_SMEM>>>(thh, thl, phh, phl, ghh, ghl,
                                                     y_hi, y_lo);

    // wy[c,n] = w_w[c,:] . y[n,:] + w_b[c]
    mma_wy<<<dim3(32, 2, BATCH), 256, SMEM_WY>>>(
        wwh, wwl, y_hi, y_lo, wy, w_b,
        DIM, DIM, NTOK, DIM / 32,
        (size_t)NTOK * DIM, (size_t)CHAN * NTOK);

    // batchnorm + residual
    bn_stats<<<CHAN, 256>>>(wy);
    bn_apply<<<(BATCH * CHAN * NTOK / 4) / 256, 256>>>(wy, x, gamma, beta, out);
}

// round 7
// speedup vs baseline: 3.3772x; 1.1180x over previous
#include <cuda_runtime.h>
#include <cuda_bf16.h>
#include <cstdint>
#include <math.h>

#define BATCH 4
#define CHAN  256
#define DIM   128
#define NTOK  4096

// ============================ scratch ============================
__device__ __nv_bfloat16 g_xt_hi[BATCH * NTOK * CHAN];   // x^T token-major [n,c]
__device__ __nv_bfloat16 g_xt_lo[BATCH * NTOK * CHAN];
__device__ __nv_bfloat16 g_th_hi[BATCH * NTOK * DIM];    // theta token-major [n,d]
__device__ __nv_bfloat16 g_th_lo[BATCH * NTOK * DIM];
__device__ __nv_bfloat16 g_ph_hi[BATCH * NTOK * DIM];    // phi token-major [m,d]
__device__ __nv_bfloat16 g_ph_lo[BATCH * NTOK * DIM];
__device__ __nv_bfloat16 g_g_hi[BATCH * DIM * NTOK];     // g d-major [d,m]
__device__ __nv_bfloat16 g_g_lo[BATCH * DIM * NTOK];
__device__ __nv_bfloat16 g_y_hi[BATCH * NTOK * DIM];     // y token-major [n,d]
__device__ __nv_bfloat16 g_y_lo[BATCH * NTOK * DIM];
__device__ __nv_bfloat16 g_wt_hi[DIM * CHAN], g_wt_lo[DIM * CHAN];   // theta_w
__device__ __nv_bfloat16 g_wp_hi[DIM * CHAN], g_wp_lo[DIM * CHAN];   // phi_w
__device__ __nv_bfloat16 g_wg_hi[DIM * CHAN], g_wg_lo[DIM * CHAN];   // g_w
__device__ __nv_bfloat16 g_ww_hi[CHAN * DIM], g_ww_lo[CHAN * DIM];   // w_w
__device__ float g_wy[BATCH * CHAN * NTOK];
__device__ float g_mean[CHAN];
__device__ float g_istd[CHAN];

// ============================ helpers ============================
__device__ __forceinline__ uint32_t smem_to_u32(const void* p) {
    uint32_t a;
    asm("{ .reg .u64 t; cvta.to.shared.u64 t, %1; cvt.u32.u64 %0, t; }" : "=r"(a) : "l"(p));
    return a;
}
__device__ __forceinline__ void cpa16(uint32_t saddr, const void* g) {
    asm volatile("cp.async.cg.shared.global [%0], [%1], 16;" :: "r"(saddr), "l"(g));
}
__device__ __forceinline__ void cpa_commit() {
    asm volatile("cp.async.commit_group;" ::: "memory");
}
__device__ __forceinline__ void cpa_wait1() {
    asm volatile("cp.async.wait_group 1;" ::: "memory");
}
__device__ __forceinline__ void ldsm_x4(uint32_t* r, uint32_t addr) {
    asm volatile("ldmatrix.sync.aligned.m8n8.x4.shared.b16 {%0,%1,%2,%3}, [%4];"
                 : "=r"(r[0]), "=r"(r[1]), "=r"(r[2]), "=r"(r[3]) : "r"(addr));
}
__device__ __forceinline__ void mma_bf16(float* c, const uint32_t* a, const uint32_t* b) {
    asm volatile("mma.sync.aligned.m16n8k16.row.col.f32.bf16.bf16.f32 "
                 "{%0,%1,%2,%3}, {%4,%5,%6,%7}, {%8,%9}, {%0,%1,%2,%3};"
                 : "+f"(c[0]), "+f"(c[1]), "+f"(c[2]), "+f"(c[3])
                 : "r"(a[0]), "r"(a[1]), "r"(a[2]), "r"(a[3]), "r"(b[0]), "r"(b[1]));
}
__device__ __forceinline__ void split_write2(__nv_bfloat16* hi, __nv_bfloat16* lo,
                                             float a, float b) {
    __nv_bfloat16 h0 = __float2bfloat16_rn(a), h1 = __float2bfloat16_rn(b);
    __nv_bfloat16 l0 = __float2bfloat16_rn(a - __bfloat162float(h0));
    __nv_bfloat16 l1 = __float2bfloat16_rn(b - __bfloat162float(h1));
    *(__nv_bfloat162*)hi = __nv_bfloat162(h0, h1);
    *(__nv_bfloat162*)lo = __nv_bfloat162(l0, l1);
}
__device__ __forceinline__ uint32_t pack_split(float a, float b, uint32_t& lo_out) {
    __nv_bfloat16 ha = __float2bfloat16_rn(a), hb = __float2bfloat16_rn(b);
    __nv_bfloat16 la = __float2bfloat16_rn(a - __bfloat162float(ha));
    __nv_bfloat16 lb = __float2bfloat16_rn(b - __bfloat162float(hb));
    __nv_bfloat162 h(ha, hb), l(la, lb);
    lo_out = *(uint32_t*)&l;
    return *(uint32_t*)&h;
}

// ============================ x transpose + split ============================
// x [B][C][N] fp32 -> xT [B][N][C] bf16 hi/lo
__global__ __launch_bounds__(256)
void x_split_T(const float* __restrict__ x,
               __nv_bfloat16* __restrict__ hi, __nv_bfloat16* __restrict__ lo)
{
    __shared__ float tile[32][33];
    const int b = blockIdx.z, c0 = blockIdx.y * 32, n0 = blockIdx.x * 32;
    const int tr = threadIdx.x >> 5, tc = threadIdx.x & 31;
    const float* src = x + ((size_t)b * CHAN + c0) * NTOK + n0;
    #pragma unroll
    for (int i = 0; i < 4; i++)
        tile[tr + 8 * i][tc] = src[(size_t)(tr + 8 * i) * NTOK + tc];
    __syncthreads();
    __nv_bfloat16* ph = hi + ((size_t)b * NTOK + n0) * CHAN + c0;
    __nv_bfloat16* pl = lo + ((size_t)b * NTOK + n0) * CHAN + c0;
    #pragma unroll
    for (int i = 0; i < 4; i++) {
        int rn = tr + 8 * i;
        float v = tile[tc][rn];
        __nv_bfloat16 h = __float2bfloat16_rn(v);
        ph[(size_t)rn * CHAN + tc] = h;
        pl[(size_t)rn * CHAN + tc] = __float2bfloat16_rn(v - __bfloat162float(h));
    }
}

// ============================ weight split (4 matrices of 32768 floats) ============================
__global__ __launch_bounds__(256)
void weights_split(const float* __restrict__ wt, const float* __restrict__ wp,
                   const float* __restrict__ wg, const float* __restrict__ ww,
                   __nv_bfloat16* __restrict__ th, __nv_bfloat16* __restrict__ tl,
                   __nv_bfloat16* __restrict__ ph, __nv_bfloat16* __restrict__ pl,
                   __nv_bfloat16* __restrict__ gh, __nv_bfloat16* __restrict__ gl,
                   __nv_bfloat16* __restrict__ wh, __nv_bfloat16* __restrict__ wl)
{
    int idx = blockIdx.x * 256 + threadIdx.x;         // 0..32767
    const float* srcs[4] = {wt, wp, wg, ww};
    __nv_bfloat16* his[4] = {th, ph, gh, wh};
    __nv_bfloat16* los[4] = {tl, pl, gl, wl};
    #pragma unroll
    for (int s = 0; s < 4; s++) {
        float v = srcs[s][idx];
        __nv_bfloat16 h = __float2bfloat16_rn(v);
        his[s][idx] = h;
        los[s][idx] = __float2bfloat16_rn(v - __bfloat162float(h));
    }
}

// ============================ unified pipelined mma.sync GEMM ============================
// C[m,n] = sum_k A[m,k]*B[n,k] (both row-major over K), split bf16 3-pass, 2-stage cp.async.
// EPI: 0 = split bf16 out + bias[col], 1 = split bf16 out + bias[row], 2 = fp32 out + bias[row]
template<int EPI>
__global__ __launch_bounds__(256, 2)
void mma_tt(const __nv_bfloat16* __restrict__ Ah, const __nv_bfloat16* __restrict__ Al,
            const __nv_bfloat16* __restrict__ Bh, const __nv_bfloat16* __restrict__ Bl,
            float* __restrict__ C, __nv_bfloat16* __restrict__ Ch, __nv_bfloat16* __restrict__ Cl,
            const float* __restrict__ bias,
            int lda, int ldb, int ldc, int kchunks,
            size_t strA, size_t strB, size_t strC)
{
    constexpr int A_BYTES = 128 * 80;
    constexpr int B_BYTES = 128 * 80;
    constexpr int SS = 2 * A_BYTES + 2 * B_BYTES;

    extern __shared__ char smem[];
    const uint32_t sb = smem_to_u32(smem);

    const int tid = threadIdx.x;
    const int lane = tid & 31, wid = tid >> 5;
    const int wr = wid >> 2;
    const int wc = wid & 3;
    const int b  = blockIdx.z;
    const int m0 = blockIdx.y * 128;
    const int n0 = blockIdx.x * 128;

    const __nv_bfloat16* pAh = Ah + (size_t)b * strA + (size_t)m0 * lda;
    const __nv_bfloat16* pAl = Al + (size_t)b * strA + (size_t)m0 * lda;
    const __nv_bfloat16* pBh = Bh + (size_t)b * strB + (size_t)n0 * ldb;
    const __nv_bfloat16* pBl = Bl + (size_t)b * strB + (size_t)n0 * ldb;

    float acc[4][4][4] = {};

    const int a_rl = ((lane >> 3) & 1) * 8 + (lane & 7);
    const int a_cl = lane >> 4;
    const int b_rl = (lane >> 4) * 8 + (lane & 7);
    const int b_cl = (lane >> 3) & 1;

    auto load_stage = [&](int s, int kc) {
        const uint32_t st = sb + s * SS;
        const int k0 = kc * 32;
        #pragma unroll
        for (int i = tid; i < 512; i += 256) {
            int r = i >> 2, c = i & 3;
            uint32_t so = st + r * 80 + c * 16;
            size_t g = (size_t)r * lda + k0 + c * 8;
            cpa16(so,           pAh + g);
            cpa16(so + A_BYTES, pAl + g);
        }
        #pragma unroll
        for (int i = tid; i < 512; i += 256) {
            int r = i >> 2, c = i & 3;
            uint32_t so = st + 2 * A_BYTES + r * 80 + c * 16;
            size_t g = (size_t)r * ldb + k0 + c * 8;
            cpa16(so,           pBh + g);
            cpa16(so + B_BYTES, pBl + g);
        }
    };

    load_stage(0, 0); cpa_commit();
    if (kchunks > 1) load_stage(1, 1);
    cpa_commit();

    for (int kc = 0; kc < kchunks; kc++) {
        cpa_wait1();
        __syncthreads();
        const uint32_t st = sb + (kc & 1) * SS;
        const uint32_t uAh = st, uAl = st + A_BYTES;
        const uint32_t uBh = st + 2 * A_BYTES, uBl = uBh + B_BYTES;

        #pragma unroll
        for (int ks = 0; ks < 2; ks++) {
            const int kk8 = ks * 2;
            uint32_t bh[4][2], bl[4][2];
            #pragma unroll
            for (int j2 = 0; j2 < 2; j2++) {
                int nrow = wc * 32 + j2 * 16 + b_rl;
                uint32_t off = (uint32_t)(nrow * 80 + (kk8 + b_cl) * 16);
                uint32_t r[4];
                ldsm_x4(r, uBh + off);
                bh[j2 * 2 + 0][0] = r[0]; bh[j2 * 2 + 0][1] = r[1];
                bh[j2 * 2 + 1][0] = r[2]; bh[j2 * 2 + 1][1] = r[3];
                ldsm_x4(r, uBl + off);
                bl[j2 * 2 + 0][0] = r[0]; bl[j2 * 2 + 0][1] = r[1];
                bl[j2 * 2 + 1][0] = r[2]; bl[j2 * 2 + 1][1] = r[3];
            }
            #pragma unroll
            for (int t = 0; t < 4; t++) {
                int mrow = wr * 64 + t * 16 + a_rl;
                uint32_t off = (uint32_t)(mrow * 80 + (kk8 + a_cl) * 16);
                uint32_t ah[4], al[4];
                ldsm_x4(ah, uAh + off);
                ldsm_x4(al, uAl + off);
                #pragma unroll
                for (int j = 0; j < 4; j++) mma_bf16(acc[t][j], ah, bh[j]);
                #pragma unroll
                for (int j = 0; j < 4; j++) mma_bf16(acc[t][j], ah, bl[j]);
                #pragma unroll
                for (int j = 0; j < 4; j++) mma_bf16(acc[t][j], al, bh[j]);
            }
        }
        __syncthreads();
        int nk = kc + 2;
        if (nk < kchunks) load_stage(kc & 1, nk);
        cpa_commit();
    }

    #pragma unroll
    for (int t = 0; t < 4; t++) {
        int row = m0 + wr * 64 + t * 16 + (lane >> 2);
        #pragma unroll
        for (int j = 0; j < 4; j++) {
            int col = n0 + wc * 32 + j * 8 + ((lane & 3) << 1);
            if (EPI == 2) {
                float* Cp = C + (size_t)b * strC;
                float b0 = bias[row], b1 = bias[row + 8];
                *(float2*)(Cp + (size_t)row * ldc + col) =
                    make_float2(acc[t][j][0] + b0, acc[t][j][1] + b0);
                *(float2*)(Cp + (size_t)(row + 8) * ldc + col) =
                    make_float2(acc[t][j][2] + b1, acc[t][j][3] + b1);
            } else {
                __nv_bfloat16* ph = Ch + (size_t)b * strC;
                __nv_bfloat16* pl = Cl + (size_t)b * strC;
                float c0, c1, r0, r1;
                if (EPI == 0) { c0 = bias[col]; c1 = bias[col + 1]; r0 = c0; r1 = c1;
                    split_write2(ph + (size_t)row * ldc + col, pl + (size_t)row * ldc + col,
                                 acc[t][j][0] + c0, acc[t][j][1] + c1);
                    split_write2(ph + (size_t)(row + 8) * ldc + col, pl + (size_t)(row + 8) * ldc + col,
                                 acc[t][j][2] + c0, acc[t][j][3] + c1);
                } else {
                    r0 = bias[row]; r1 = bias[row + 8];
                    split_write2(ph + (size_t)row * ldc + col, pl + (size_t)row * ldc + col,
                                 acc[t][j][0] + r0, acc[t][j][1] + r0);
                    split_write2(ph + (size_t)(row + 8) * ldc + col, pl + (size_t)(row + 8) * ldc + col,
                                 acc[t][j][2] + r1, acc[t][j][3] + r1);
                }
            }
        }
    }
}

// ============================ fused attention kernel ============================
#define TH_STR   272
#define PHI_STR  272
#define G_STR    144
#define TH_HALF  (128 * TH_STR)
#define TH_BYTES (2 * TH_HALF)
#define PHI_HALF (64 * PHI_STR)
#define PHI_STAGE (2 * PHI_HALF)
#define G_HALF   (128 * G_STR)
#define G_STAGE  (2 * G_HALF)
#define PHI_OFF  TH_BYTES
#define G_OFF    (PHI_OFF + 2 * PHI_STAGE)
#define FUSED_SMEM (G_OFF + 2 * G_STAGE)

__global__ __launch_bounds__(256, 1)
void fused_attn(const __nv_bfloat16* __restrict__ thh, const __nv_bfloat16* __restrict__ thl,
                const __nv_bfloat16* __restrict__ phh, const __nv_bfloat16* __restrict__ phl,
                const __nv_bfloat16* __restrict__ ghh, const __nv_bfloat16* __restrict__ ghl,
                __nv_bfloat16* __restrict__ y_hi, __nv_bfloat16* __restrict__ y_lo)
{
    extern __shared__ char smem[];
    const uint32_t sb = smem_to_u32(smem);
    const int tid = threadIdx.x;
    const int lane = tid & 31, wid = tid >> 5;
    const int b = blockIdx.y;
    const int m0 = blockIdx.x * 128;

    const __nv_bfloat16* pth = thh + ((size_t)b * NTOK + m0) * DIM;
    const __nv_bfloat16* ptl = thl + ((size_t)b * NTOK + m0) * DIM;
    const __nv_bfloat16* pph = phh + (size_t)b * NTOK * DIM;
    const __nv_bfloat16* ppl = phl + (size_t)b * NTOK * DIM;
    const __nv_bfloat16* pgh = ghh + (size_t)b * DIM * NTOK;
    const __nv_bfloat16* pgl = ghl + (size_t)b * DIM * NTOK;

    #pragma unroll
    for (int i = tid; i < 4096; i += 256) {
        int h = i >> 11, rem = i & 2047;
        int r = rem >> 4, c = rem & 15;
        const __nv_bfloat16* src = h ? ptl : pth;
        cpa16(sb + h * TH_HALF + r * TH_STR + c * 16, src + (size_t)r * DIM + c * 8);
    }

    auto load_stage = [&](int s, int nt) {
        uint32_t pb = sb + PHI_OFF + s * PHI_STAGE;
        const __nv_bfloat16* sph = pph + (size_t)(nt * 64) * DIM;
        const __nv_bfloat16* spl = ppl + (size_t)(nt * 64) * DIM;
        #pragma unroll
        for (int i = tid; i < 2048; i += 256) {
            int h = i >> 10, rem = i & 1023;
            int r = rem >> 4, c = rem & 15;
            const __nv_bfloat16* src = h ? spl : sph;
            cpa16(pb + h * PHI_HALF + r * PHI_STR + c * 16, src + (size_t)r * DIM + c * 8);
        }
        uint32_t gb = sb + G_OFF + s * G_STAGE;
        const __nv_bfloat16* sgh = pgh + nt * 64;
        const __nv_bfloat16* sgl = pgl + nt * 64;
        #pragma unroll
        for (int i = tid; i < 2048; i += 256) {
            int h = i >> 10, rem = i & 1023;
            int r = rem >> 3, c = rem & 7;
            const __nv_bfloat16* src = h ? sgl : sgh;
            cpa16(gb + h * G_HALF + r * G_STR + c * 16, src + (size_t)r * NTOK + c * 8);
        }
    };

    load_stage(0, 0); cpa_commit();
    load_stage(1, 1); cpa_commit();

    float yacc[16][4] = {};
    float rs0 = 0.0f, rs1 = 0.0f;

    const int a_rl = ((lane >> 3) & 1) * 8 + (lane & 7);
    const int a_cl = lane >> 4;
    const int b_rl = (lane >> 4) * 8 + (lane & 7);
    const int b_cl = (lane >> 3) & 1;
    const uint32_t a_base = sb + (uint32_t)(16 * wid + a_rl) * TH_STR + a_cl * 16;

    for (int nt = 0; nt < 64; nt++) {
        cpa_wait1();
        __syncthreads();
        const uint32_t uph = sb + PHI_OFF + (nt & 1) * PHI_STAGE;
        const uint32_t ug  = sb + G_OFF + (nt & 1) * G_STAGE;

        // ---- S = theta . phi^T over K=128 (8 ksteps), 3-pass ----
        float S[8][4] = {};
        #pragma unroll
        for (int ks = 0; ks < 8; ks++) {
            uint32_t ath[4], atl[4];
            uint32_t aoff = a_base + ks * 32;
            ldsm_x4(ath, aoff);
            ldsm_x4(atl, aoff + TH_HALF);
            uint32_t bh[8][2], bl[8][2];
            #pragma unroll
            for (int f = 0; f < 4; f++) {
                uint32_t boff = (uint32_t)(16 * f + b_rl) * PHI_STR + (2 * ks + b_cl) * 16;
                uint32_t r[4];
                ldsm_x4(r, uph + boff);
                bh[2 * f][0] = r[0]; bh[2 * f][1] = r[1];
                bh[2 * f + 1][0] = r[2]; bh[2 * f + 1][1] = r[3];
                ldsm_x4(r, uph + PHI_HALF + boff);
                bl[2 * f][0] = r[0]; bl[2 * f][1] = r[1];
                bl[2 * f + 1][0] = r[2]; bl[2 * f + 1][1] = r[3];
            }
            #pragma unroll
            for (int j = 0; j < 8; j++) mma_bf16(S[j], ath, bh[j]);
            #pragma unroll
            for (int j = 0; j < 8; j++) mma_bf16(S[j], ath, bl[j]);
            #pragma unroll
            for (int j = 0; j < 8; j++) mma_bf16(S[j], atl, bh[j]);
        }

        // ---- interleaved: per-ks2 {g frags -> exp/pack -> PV MMA} ----
        #pragma unroll
        for (int ks2 = 0; ks2 < 4; ks2++) {
            uint32_t gh[16][2], gl[16][2];
            #pragma unroll
            for (int dd = 0; dd < 8; dd++) {
                uint32_t boff = (uint32_t)(16 * dd + b_rl) * G_STR + (2 * ks2 + b_cl) * 16;
                uint32_t r[4];
                ldsm_x4(r, ug + boff);
                gh[2 * dd][0] = r[0]; gh[2 * dd][1] = r[1];
                gh[2 * dd + 1][0] = r[2]; gh[2 * dd + 1][1] = r[3];
                ldsm_x4(r, ug + G_HALF + boff);
                gl[2 * dd][0] = r[0]; gl[2 * dd][1] = r[1];
                gl[2 * dd + 1][0] = r[2]; gl[2 * dd + 1][1] = r[3];
            }
            float e0 = __expf(S[2 * ks2][0]),     e1 = __expf(S[2 * ks2][1]);
            float e2 = __expf(S[2 * ks2][2]),     e3 = __expf(S[2 * ks2][3]);
            float e4 = __expf(S[2 * ks2 + 1][0]), e5 = __expf(S[2 * ks2 + 1][1]);
            float e6 = __expf(S[2 * ks2 + 1][2]), e7 = __expf(S[2 * ks2 + 1][3]);
            rs0 += (e0 + e1) + (e4 + e5);
            rs1 += (e2 + e3) + (e6 + e7);
            uint32_t Ph[4], Pl[4];
            Ph[0] = pack_split(e0, e1, Pl[0]);
            Ph[1] = pack_split(e2, e3, Pl[1]);
            Ph[2] = pack_split(e4, e5, Pl[2]);
            Ph[3] = pack_split(e6, e7, Pl[3]);
            #pragma unroll
            for (int j = 0; j < 16; j++) mma_bf16(yacc[j], Ph, gh[j]);
            #pragma unroll
            for (int j = 0; j < 16; j++) mma_bf16(yacc[j], Ph, gl[j]);
            #pragma unroll
            for (int j = 0; j < 16; j++) mma_bf16(yacc[j], Pl, gh[j]);
        }

        __syncthreads();
        if (nt + 2 < 64) load_stage(nt & 1, nt + 2);
        cpa_commit();
    }

    rs0 += __shfl_xor_sync(0xffffffffu, rs0, 1);
    rs0 += __shfl_xor_sync(0xffffffffu, rs0, 2);
    rs1 += __shfl_xor_sync(0xffffffffu, rs1, 1);
    rs1 += __shfl_xor_sync(0xffffffffu, rs1, 2);
    float inv0 = 1.0f / rs0, inv1 = 1.0f / rs1;

    int row = m0 + 16 * wid + (lane >> 2);
    __nv_bfloat16* yh = y_hi + (size_t)b * NTOK * DIM;
    __nv_bfloat16* yl = y_lo + (size_t)b * NTOK * DIM;
    #pragma unroll
    for (int j = 0; j < 16; j++) {
        int col = 8 * j + 2 * (lane & 3);
        split_write2(yh + (size_t)row * DIM + col, yl + (size_t)row * DIM + col,
                     yacc[j][0] * inv0, yacc[j][1] * inv0);
        split_write2(yh + (size_t)(row + 8) * DIM + col, yl + (size_t)(row + 8) * DIM + col,
                     yacc[j][2] * inv1, yacc[j][3] * inv1);
    }
}

// ============================ batchnorm ============================
__global__ __launch_bounds__(256)
void bn_stats(const float* __restrict__ wy)
{
    const int c = blockIdx.x;
    const int t = threadIdx.x;
    float s1 = 0.0f, s2 = 0.0f;
    #pragma unroll
    for (int b = 0; b < BATCH; b++) {
        const float* p = wy + ((size_t)(b * CHAN + c) << 12);
        for (int i = t; i < NTOK; i += 256) {
            float x = p[i];
            s1 += x; s2 += x * x;
        }
    }
    #pragma unroll
    for (int o = 16; o; o >>= 1) {
        s1 += __shfl_xor_sync(0xffffffffu, s1, o);
        s2 += __shfl_xor_sync(0xffffffffu, s2, o);
    }
    __shared__ float r1[8], r2[8];
    if ((t & 31) == 0) { r1[t >> 5] = s1; r2[t >> 5] = s2; }
    __syncthreads();
    if (t == 0) {
        s1 = 0.0f; s2 = 0.0f;
        #pragma unroll
        for (int i = 0; i < 8; i++) { s1 += r1[i]; s2 += r2[i]; }
        float mean = s1 * (1.0f / 16384.0f);
        float var  = s2 * (1.0f / 16384.0f) - mean * mean;
        g_mean[c] = mean;
        g_istd[c] = rsqrtf(var + 1e-5f);
    }
}

__global__ __launch_bounds__(256)
void bn_apply(const float* __restrict__ wy, const float* __restrict__ x,
              const float* __restrict__ gamma, const float* __restrict__ beta,
              float* __restrict__ out)
{
    int i4 = blockIdx.x * 256 + threadIdx.x;
    int c = (i4 >> 10) & (CHAN - 1);
    float is = g_istd[c];
    float ga = gamma[c] * is;
    float be = beta[c] - g_mean[c] * ga;
    float4 w = ((const float4*)wy)[i4];
    float4 xx = ((const float4*)x)[i4];
    float4 o;
    o.x = w.x * ga + be + xx.x;
    o.y = w.y * ga + be + xx.y;
    o.z = w.z * ga + be + xx.z;
    o.w = w.w * ga + be + xx.w;
    ((float4*)out)[i4] = o;
}

// ============================ launch ============================
#define SMEM_TT (2 * (2 * 128 * 80 + 2 * 128 * 80))   // 81920

extern "C" void kernel_launch(void* const* d_in, const int* in_sizes, int n_in,
                              void* d_out, int out_size)
{
    const float* x       = (const float*)d_in[0];
    const float* g_w     = (const float*)d_in[1];
    const float* g_b     = (const float*)d_in[2];
    const float* theta_w = (const float*)d_in[3];
    const float* theta_b = (const float*)d_in[4];
    const float* phi_w   = (const float*)d_in[5];
    const float* phi_b   = (const float*)d_in[6];
    const float* w_w     = (const float*)d_in[7];
    const float* w_b     = (const float*)d_in[8];
    const float* gamma   = (const float*)d_in[9];
    const float* beta    = (const float*)d_in[10];
    float* out = (float*)d_out;

    float* wy;
    __nv_bfloat16 *xth, *xtl, *thh, *thl, *phh, *phl, *ghh, *ghl, *y_hi, *y_lo;
    __nv_bfloat16 *wth, *wtl, *wph, *wpl, *wgh, *wgl, *wwh, *wwl;
    cudaGetSymbolAddress((void**)&wy,   g_wy);
    cudaGetSymbolAddress((void**)&xth,  g_xt_hi);
    cudaGetSymbolAddress((void**)&xtl,  g_xt_lo);
    cudaGetSymbolAddress((void**)&thh,  g_th_hi);
    cudaGetSymbolAddress((void**)&thl,  g_th_lo);
    cudaGetSymbolAddress((void**)&phh,  g_ph_hi);
    cudaGetSymbolAddress((void**)&phl,  g_ph_lo);
    cudaGetSymbolAddress((void**)&ghh,  g_g_hi);
    cudaGetSymbolAddress((void**)&ghl,  g_g_lo);
    cudaGetSymbolAddress((void**)&y_hi, g_y_hi);
    cudaGetSymbolAddress((void**)&y_lo, g_y_lo);
    cudaGetSymbolAddress((void**)&wth,  g_wt_hi);
    cudaGetSymbolAddress((void**)&wtl,  g_wt_lo);
    cudaGetSymbolAddress((void**)&wph,  g_wp_hi);
    cudaGetSymbolAddress((void**)&wpl,  g_wp_lo);
    cudaGetSymbolAddress((void**)&wgh,  g_wg_hi);
    cudaGetSymbolAddress((void**)&wgl,  g_wg_lo);
    cudaGetSymbolAddress((void**)&wwh,  g_ww_hi);
    cudaGetSymbolAddress((void**)&wwl,  g_ww_lo);

    cudaFuncSetAttribute(fused_attn, cudaFuncAttributeMaxDynamicSharedMemorySize, FUSED_SMEM);
    cudaFuncSetAttribute(mma_tt<0>, cudaFuncAttributeMaxDynamicSharedMemorySize, SMEM_TT);
    cudaFuncSetAttribute(mma_tt<1>, cudaFuncAttributeMaxDynamicSharedMemorySize, SMEM_TT);
    cudaFuncSetAttribute(mma_tt<2>, cudaFuncAttributeMaxDynamicSharedMemorySize, SMEM_TT);

    // split inputs
    x_split_T<<<dim3(128, 8, BATCH), 256>>>(x, xth, xtl);
    weights_split<<<128, 256>>>(theta_w, phi_w, g_w, w_w,
                                wth, wtl, wph, wpl, wgh, wgl, wwh, wwl);

    // theta[n,d] = xT[n,:] . Wt[d,:] + bt[d]   (bias over columns)
    mma_tt<0><<<dim3(1, 32, BATCH), 256, SMEM_TT>>>(
        xth, xtl, wth, wtl, nullptr, thh, thl, theta_b,
        CHAN, CHAN, DIM, CHAN / 32,
        (size_t)NTOK * CHAN, 0, (size_t)NTOK * DIM);
    // phi[m,d]
    mma_tt<0><<<dim3(1, 32, BATCH), 256, SMEM_TT>>>(
        xth, xtl, wph, wpl, nullptr, phh, phl, phi_b,
        CHAN, CHAN, DIM, CHAN / 32,
        (size_t)NTOK * CHAN, 0, (size_t)NTOK * DIM);
    // g[d,m] = Wg[d,:] . xT[m,:] + gb[d]   (bias over rows)
    mma_tt<1><<<dim3(32, 1, BATCH), 256, SMEM_TT>>>(
        wgh, wgl, xth, xtl, nullptr, ghh, ghl, g_b,
        CHAN, CHAN, NTOK, CHAN / 32,
        0, (size_t)NTOK * CHAN, (size_t)DIM * NTOK);

    // fused attention
    fused_attn<<<dim3(32, BATCH), 256, FUSED_SMEM>>>(thh, thl, phh, phl, ghh, ghl,
                                                     y_hi, y_lo);

    // wy[c,n] = w_w[c,:] . y[n,:] + w_b[c]
    mma_tt<2><<<dim3(32, 2, BATCH), 256, SMEM_TT>>>(
        wwh, wwl, y_hi, y_lo, wy, nullptr, nullptr, w_b,
        DIM, DIM, NTOK, DIM / 32,
        0, (size_t)NTOK * DIM, (size_t)CHAN * NTOK);

    // batchnorm + residual
    bn_stats<<<CHAN, 256>>>(wy);
    bn_apply<<<(BATCH * CHAN * NTOK / 4) / 256, 256>>>(wy, x, gamma, beta, out);
}